// round 1
// baseline (speedup 1.0000x reference)
#include <cuda_runtime.h>
#include <math.h>

#define NN 131072

// ---------------- scratch (static device memory; no allocation) ----------------
__device__ float g_gi [(size_t)NN * 768];   // gate pre-activations (reused L1/L2)
__device__ float g_h1 [(size_t)NN * 256];
__device__ float g_h2 [(size_t)NN * 256];
__device__ float g_xw1[(size_t)NN * 128];
__device__ float g_g1b[(size_t)NN * 128];
__device__ float g_xw2[(size_t)NN * 64];
__device__ float g_g2b[(size_t)NN * 64];
__device__ float g_wg1t[128 * 256];
__device__ float g_wg2t[64 * 128];
__device__ float g_wfct[10 * 64];

// ---------------- small transpose: src[R,C] -> dst[C,R] ----------------
__global__ void transpose_k(const float* __restrict__ src, float* __restrict__ dst,
                            int R, int C) {
    int idx = blockIdx.x * blockDim.x + threadIdx.x;
    if (idx < R * C) {
        int r = idx / C, c = idx % C;
        dst[c * R + r] = src[idx];
    }
}

// ---------------- tiled fp32 GEMM: C[M,Nc] = A[M,K] @ Bt[Nc,K]^T (+bias) ----------------
#define BM 128
#define BN 64
#define BK 16
#define TM 8
#define TN 4

__global__ void __launch_bounds__(256)
gemm_bt(const float* __restrict__ A, int lda,
        const float* __restrict__ Bt,
        const float* __restrict__ bias,
        float* __restrict__ C, int ldc,
        int M, int Nc, int K)
{
    __shared__ float As[BK][BM];
    __shared__ float Bs[BK][BN];

    int tid = threadIdx.x;
    int tx = tid & 15;        // 16 column-thread groups
    int ty = tid >> 4;        // 16 row-thread groups
    int mBase = blockIdx.y * BM;
    int nBase = blockIdx.x * BN;

    float acc[TM][TN];
#pragma unroll
    for (int i = 0; i < TM; i++)
#pragma unroll
        for (int j = 0; j < TN; j++) acc[i][j] = 0.f;

    int la_row = tid >> 2;           // 0..63
    int la_c4  = (tid & 3) * 4;      // 0,4,8,12

    for (int k0 = 0; k0 < K; k0 += BK) {
        // A tile: 128x16 (two 64-row halves), float4 loads, store transposed
#pragma unroll
        for (int h = 0; h < 2; h++) {
            int row = la_row + h * 64;
            const float4 v = *reinterpret_cast<const float4*>(
                A + (size_t)(mBase + row) * lda + k0 + la_c4);
            As[la_c4 + 0][row] = v.x;
            As[la_c4 + 1][row] = v.y;
            As[la_c4 + 2][row] = v.z;
            As[la_c4 + 3][row] = v.w;
        }
        // B tile: 64x16
        {
            int n = nBase + la_row;
            float4 v = make_float4(0.f, 0.f, 0.f, 0.f);
            if (n < Nc)
                v = *reinterpret_cast<const float4*>(Bt + (size_t)n * K + k0 + la_c4);
            Bs[la_c4 + 0][la_row] = v.x;
            Bs[la_c4 + 1][la_row] = v.y;
            Bs[la_c4 + 2][la_row] = v.z;
            Bs[la_c4 + 3][la_row] = v.w;
        }
        __syncthreads();

#pragma unroll
        for (int k = 0; k < BK; k++) {
            float4 a0 = *reinterpret_cast<const float4*>(&As[k][ty * TM]);
            float4 a1 = *reinterpret_cast<const float4*>(&As[k][ty * TM + 4]);
            float4 b  = *reinterpret_cast<const float4*>(&Bs[k][tx * TN]);
            float am[TM] = {a0.x, a0.y, a0.z, a0.w, a1.x, a1.y, a1.z, a1.w};
            float bn[TN] = {b.x, b.y, b.z, b.w};
#pragma unroll
            for (int i = 0; i < TM; i++)
#pragma unroll
                for (int j = 0; j < TN; j++)
                    acc[i][j] = fmaf(am[i], bn[j], acc[i][j]);
        }
        __syncthreads();
    }

#pragma unroll
    for (int i = 0; i < TM; i++) {
        int m = mBase + ty * TM + i;
#pragma unroll
        for (int j = 0; j < TN; j++) {
            int n = nBase + tx * TN + j;
            if (n < Nc) {
                float v = acc[i][j];
                if (bias) v += bias[n];
                C[(size_t)m * ldc + n] = v;
            }
        }
    }
}

// ---------------- GRU gate activation (h_prev = 0) ----------------
// gi layout per row: [f_r(128) f_z f_n | b_r b_z b_n] (768)
// h layout per row:  [h_fwd(128) | h_bwd(128)] (256)
__global__ void gru_act(const float* __restrict__ gi,
                        const float* __restrict__ bhf,
                        const float* __restrict__ bhb,
                        float* __restrict__ h, int n)
{
    int idx = blockIdx.x * blockDim.x + threadIdx.x;
    if (idx >= n * 256) return;
    int i = idx >> 8;
    int j = idx & 255;
    const float* bh = (j < 128) ? bhf : bhb;
    int jj = j & 127;
    size_t base = (size_t)i * 768 + (j < 128 ? 0 : 384);
    float ir = gi[base + jj];
    float iz = gi[base + 128 + jj];
    float in = gi[base + 256 + jj];
    float r  = 1.f / (1.f + expf(-(ir + bh[jj])));
    float z  = 1.f / (1.f + expf(-(iz + bh[128 + jj])));
    float ng = tanhf(in + r * bh[256 + jj]);
    h[idx] = (1.f - z) * ng;
}

// ---------------- GCN chain stencil: out[i] = dinv[i]*(sum_j dinv[j]*xw[j]) + b ----------------
__global__ void gcn_stencil(const float* __restrict__ xw,
                            const float* __restrict__ bias,
                            float* __restrict__ out, int C, int n)
{
    int idx = blockIdx.x * blockDim.x + threadIdx.x;
    if (idx >= n * C) return;
    int i = idx / C;
    int c = idx - i * C;
    float deg_i = 1.f + (float)(i > 0) + (float)(i < n - 1);
    float di = rsqrtf(deg_i);
    float acc = di * xw[idx];
    if (i > 0) {
        float degm = 2.f + (float)(i - 1 > 0);          // i-1 < n-1 always here
        acc += rsqrtf(degm) * xw[idx - C];
    }
    if (i < n - 1) {
        float degp = 2.f + (float)(i + 1 < n - 1);      // i+1 > 0 always here
        acc += rsqrtf(degp) * xw[idx + C];
    }
    out[idx] = di * acc + bias[c];
}

// ---------------- launch ----------------
extern "C" void kernel_launch(void* const* d_in, const int* in_sizes, int n_in,
                              void* d_out, int out_size)
{
    const float* x        = (const float*)d_in[0];
    const float* w_ih_f1  = (const float*)d_in[1];
    const float* b_ih_f1  = (const float*)d_in[2];
    const float* b_hh_f1  = (const float*)d_in[3];
    const float* w_ih_b1  = (const float*)d_in[4];
    const float* b_ih_b1  = (const float*)d_in[5];
    const float* b_hh_b1  = (const float*)d_in[6];
    const float* w_ih_f2  = (const float*)d_in[7];
    const float* b_ih_f2  = (const float*)d_in[8];
    const float* b_hh_f2  = (const float*)d_in[9];
    const float* w_ih_b2  = (const float*)d_in[10];
    const float* b_ih_b2  = (const float*)d_in[11];
    const float* b_hh_b2  = (const float*)d_in[12];
    const float* w_g1     = (const float*)d_in[13];
    const float* b_g1     = (const float*)d_in[14];
    const float* w_g2     = (const float*)d_in[15];
    const float* b_g2     = (const float*)d_in[16];
    const float* w_fc     = (const float*)d_in[17];
    const float* b_fc     = (const float*)d_in[18];
    float* out = (float*)d_out;

    float *gi, *h1, *h2, *xw1, *g1b, *xw2, *g2b, *wg1t, *wg2t, *wfct;
    cudaGetSymbolAddress((void**)&gi,   g_gi);
    cudaGetSymbolAddress((void**)&h1,   g_h1);
    cudaGetSymbolAddress((void**)&h2,   g_h2);
    cudaGetSymbolAddress((void**)&xw1,  g_xw1);
    cudaGetSymbolAddress((void**)&g1b,  g_g1b);
    cudaGetSymbolAddress((void**)&xw2,  g_xw2);
    cudaGetSymbolAddress((void**)&g2b,  g_g2b);
    cudaGetSymbolAddress((void**)&wg1t, g_wg1t);
    cudaGetSymbolAddress((void**)&wg2t, g_wg2t);
    cudaGetSymbolAddress((void**)&wfct, g_wfct);

    // transpose small GCN / fc weights to [out, K] row-major form
    transpose_k<<<(256 * 128 + 255) / 256, 256>>>(w_g1, wg1t, 256, 128);
    transpose_k<<<(128 * 64 + 255) / 256, 256>>>(w_g2, wg2t, 128, 64);
    transpose_k<<<(64 * 10 + 255) / 256, 256>>>(w_fc, wfct, 64, 10);

    dim3 blk(256);
    dim3 grid6(384 / BN, NN / BM);

    // GRU layer 1: gi = x @ [w_ih_f1; w_ih_b1]^T + b_ih
    gemm_bt<<<grid6, blk>>>(x, 128, w_ih_f1, b_ih_f1, gi,       768, NN, 384, 128);
    gemm_bt<<<grid6, blk>>>(x, 128, w_ih_b1, b_ih_b1, gi + 384, 768, NN, 384, 128);
    gru_act<<<(NN * 256) / 256, blk>>>(gi, b_hh_f1, b_hh_b1, h1, NN);

    // GRU layer 2 (input h1 [N,256])
    gemm_bt<<<grid6, blk>>>(h1, 256, w_ih_f2, b_ih_f2, gi,       768, NN, 384, 256);
    gemm_bt<<<grid6, blk>>>(h1, 256, w_ih_b2, b_ih_b2, gi + 384, 768, NN, 384, 256);
    gru_act<<<(NN * 256) / 256, blk>>>(gi, b_hh_f2, b_hh_b2, h2, NN);

    // GCN layer 1: xw1 = h2 @ w_g1 ; chain stencil + bias
    gemm_bt<<<dim3(128 / BN, NN / BM), blk>>>(h2, 256, wg1t, nullptr, xw1, 128, NN, 128, 256);
    gcn_stencil<<<(NN * 128) / 256, blk>>>(xw1, b_g1, g1b, 128, NN);

    // GCN layer 2: xw2 = g1 @ w_g2 ; stencil + bias
    gemm_bt<<<dim3(64 / BN, NN / BM), blk>>>(g1b, 128, wg2t, nullptr, xw2, 64, NN, 64, 128);
    gcn_stencil<<<(NN * 64) / 256, blk>>>(xw2, b_g2, g2b, 64, NN);

    // final fc: out = g2 @ w_fc + b_fc
    gemm_bt<<<dim3(1, NN / BM), blk>>>(g2b, 64, wfct, b_fc, out, 10, NN, 10, 64);
}

// round 4
// speedup vs baseline: 1.6100x; 1.6100x over previous
#include <cuda_runtime.h>
#include <cuda_bf16.h>
#include <math.h>
#include <stdint.h>

#define NN 131072

// ---------------- static device scratch ----------------
__device__ float         g_gi [(size_t)NN * 768];
__device__ __nv_bfloat16 g_xhi[(size_t)NN * 128], g_xlo[(size_t)NN * 128];
__device__ __nv_bfloat16 g_h1hi[(size_t)NN * 256], g_h1lo[(size_t)NN * 256];
__device__ __nv_bfloat16 g_h2hi[(size_t)NN * 256], g_h2lo[(size_t)NN * 256];
__device__ float         g_xw1[(size_t)NN * 128];
__device__ __nv_bfloat16 g_g1hi[(size_t)NN * 128], g_g1lo[(size_t)NN * 128];
__device__ float         g_xw2[(size_t)NN * 64];
__device__ float         g_g2 [(size_t)NN * 64];
__device__ __nv_bfloat16 g_w1fhi[384 * 128], g_w1flo[384 * 128];
__device__ __nv_bfloat16 g_w1bhi[384 * 128], g_w1blo[384 * 128];
__device__ __nv_bfloat16 g_w2fhi[384 * 256], g_w2flo[384 * 256];
__device__ __nv_bfloat16 g_w2bhi[384 * 256], g_w2blo[384 * 256];
__device__ __nv_bfloat16 g_wg1hi[128 * 256], g_wg1lo[128 * 256];
__device__ __nv_bfloat16 g_wg2hi[64 * 128],  g_wg2lo[64 * 128];
__device__ float         g_wfct[10 * 64];

// ---------------- PTX helpers (baseline PTX only; no tcgen05) ----------------
__device__ __forceinline__ uint32_t smem_u32(const void* p) {
    uint32_t a;
    asm("{ .reg .u64 t; cvta.to.shared.u64 t, %1; cvt.u32.u64 %0, t; }" : "=r"(a) : "l"(p));
    return a;
}
__device__ __forceinline__ void cp16(uint32_t dst, const void* src) {
    asm volatile("cp.async.cg.shared.global [%0], [%1], 16;" :: "r"(dst), "l"(src));
}
__device__ __forceinline__ void cp_commit() {
    asm volatile("cp.async.commit_group;");
}
__device__ __forceinline__ void cp_wait2() {
    asm volatile("cp.async.wait_group 2;");
}
__device__ __forceinline__ void ldm_x4(uint32_t& r0, uint32_t& r1, uint32_t& r2, uint32_t& r3,
                                       uint32_t addr) {
    asm volatile("ldmatrix.sync.aligned.m8n8.x4.shared.b16 {%0,%1,%2,%3}, [%4];"
                 : "=r"(r0), "=r"(r1), "=r"(r2), "=r"(r3) : "r"(addr));
}
__device__ __forceinline__ void mma_bf16(float* d, const uint32_t* a, const uint32_t* b) {
    asm volatile("mma.sync.aligned.m16n8k16.row.col.f32.bf16.bf16.f32 "
                 "{%0,%1,%2,%3}, {%4,%5,%6,%7}, {%8,%9}, {%0,%1,%2,%3};"
                 : "+f"(d[0]), "+f"(d[1]), "+f"(d[2]), "+f"(d[3])
                 : "r"(a[0]), "r"(a[1]), "r"(a[2]), "r"(a[3]), "r"(b[0]), "r"(b[1]));
}
__device__ __forceinline__ float sigmoidf_(float x) { return 1.f / (1.f + expf(-x)); }

// ---------------- 3-plane bf16 MMA GEMM: C[M, Nc] = A@B^T (+bias) ----------------
// A planes [M,K] K-major, B planes [Nc,K] K-major. Virtual K' = 3K:
// plane 0: Ah*Bh, plane 1: Al*Bh, plane 2: Ah*Bl. fp32 accumulate, fp32 out.
// CTA tile 128 x NT. 8 warps: wy in {0,1} (64 M-rows), wx in 0..3 (NT/4 cols).
template <int NT>
__global__ void __launch_bounds__(256, 2)
gemm3(const __nv_bfloat16* __restrict__ Ahi, const __nv_bfloat16* __restrict__ Alo, int K,
      const __nv_bfloat16* __restrict__ Bhi, const __nv_bfloat16* __restrict__ Blo,
      const float* __restrict__ bias, float* __restrict__ C, int ldc)
{
    extern __shared__ char sm[];
    constexpr int AST = 80;                 // padded row stride (bytes) for 32 bf16
    constexpr int ABYTES = 128 * AST;       // 10240
    constexpr int BBYTES = NT * AST;
    constexpr int STAGE = ABYTES + BBYTES;
    constexpr int NJ = NT / 32;             // n8 tiles per warp (4 or 2)

    const int tid = threadIdx.x, lane = tid & 31, wid = tid >> 5;
    const int wy = wid & 1, wx = wid >> 1;
    const int mBase = blockIdx.x * 128;
    const int nBase = blockIdx.y * NT;
    const int KC = K >> 5;                  // 32-chunks per plane
    const int NCH = 3 * KC;

    const uint32_t sbase = smem_u32(sm);
    const int arow = tid >> 1, acol = (tid & 1) * 2;
    const int brow64 = tid >> 2, bch64 = tid & 3;

    auto issue = [&](int c) {
        int p = c / KC;
        int kk = (c - p * KC) * 32;
        const __nv_bfloat16* A = (p == 1) ? Alo : Ahi;
        const __nv_bfloat16* B = (p == 2) ? Blo : Bhi;
        uint32_t st = sbase + (c & 3) * STAGE;
        const __nv_bfloat16* ga = A + (size_t)(mBase + arow) * K + kk + acol * 8;
        uint32_t da = st + arow * AST + acol * 16;
        cp16(da, ga);
        cp16(da + 16, ga + 8);
        if (NT == 128) {
            const __nv_bfloat16* gb = B + (size_t)(nBase + arow) * K + kk + acol * 8;
            uint32_t db = st + ABYTES + arow * AST + acol * 16;
            cp16(db, gb);
            cp16(db + 16, gb + 8);
        } else {
            const __nv_bfloat16* gb = B + (size_t)(nBase + brow64) * K + kk + bch64 * 8;
            cp16(st + ABYTES + brow64 * AST + bch64 * 16, gb);
        }
        cp_commit();
    };

    float acc[4][NJ][4];
#pragma unroll
    for (int i = 0; i < 4; i++)
#pragma unroll
        for (int j = 0; j < NJ; j++)
#pragma unroll
            for (int q = 0; q < 4; q++) acc[i][j][q] = 0.f;

    issue(0); issue(1); issue(2);

    const uint32_t a_lrow = (lane & 15), a_khalf = (lane >> 4) * 16;
    for (int c = 0; c < NCH; c++) {
        cp_wait2();
        __syncthreads();
        // Exactly ONE commit per iteration (empty group past the end) so that
        // wait_group 2 always guarantees chunk c is resident. (Round-3 bug:
        // missing tail commits made the last two chunks race.)
        if (c + 3 < NCH) issue(c + 3);
        else cp_commit();
        uint32_t st = sbase + (c & 3) * STAGE;
#pragma unroll
        for (int kh = 0; kh < 2; kh++) {
            uint32_t a[4][4];
#pragma unroll
            for (int i = 0; i < 4; i++) {
                uint32_t addr = st + (wy * 64 + i * 16 + a_lrow) * AST + kh * 32 + a_khalf;
                ldm_x4(a[i][0], a[i][1], a[i][2], a[i][3], addr);
            }
            uint32_t bf[NJ][2];
#pragma unroll
            for (int jj = 0; jj < NJ / 2; jj++) {
                uint32_t r0, r1, r2, r3;
                uint32_t addr = st + ABYTES +
                    (wx * (NT / 4) + jj * 16 + a_lrow) * AST + kh * 32 + a_khalf;
                ldm_x4(r0, r1, r2, r3, addr);
                bf[2 * jj][0] = r0; bf[2 * jj][1] = r2;
                bf[2 * jj + 1][0] = r1; bf[2 * jj + 1][1] = r3;
            }
#pragma unroll
            for (int i = 0; i < 4; i++)
#pragma unroll
                for (int j = 0; j < NJ; j++)
                    mma_bf16(acc[i][j], a[i], bf[j]);
        }
    }

    // epilogue
#pragma unroll
    for (int i = 0; i < 4; i++) {
        int r0 = mBase + wy * 64 + i * 16 + (lane >> 2);
#pragma unroll
        for (int j = 0; j < NJ; j++) {
            int col = nBase + wx * (NT / 4) + j * 8 + (lane & 3) * 2;
            float b0 = 0.f, b1 = 0.f;
            if (bias) { b0 = bias[col]; b1 = bias[col + 1]; }
            float2* p0 = (float2*)(C + (size_t)r0 * ldc + col);
            float2* p1 = (float2*)(C + (size_t)(r0 + 8) * ldc + col);
            *p0 = make_float2(acc[i][j][0] + b0, acc[i][j][1] + b1);
            *p1 = make_float2(acc[i][j][2] + b0, acc[i][j][3] + b1);
        }
    }
}

// ---------------- GRU gate activation -> bf16 hi/lo planes ----------------
// gi per row: [f_r(128) f_z f_n | b_r b_z b_n] (768). H planes [N,256].
__global__ void gru_act_split(const float* __restrict__ gi,
                              const float* __restrict__ bhf,
                              const float* __restrict__ bhb,
                              __nv_bfloat16* __restrict__ Hhi,
                              __nv_bfloat16* __restrict__ Hlo, int n)
{
    int idx = blockIdx.x * blockDim.x + threadIdx.x;
    if (idx >= n * 256) return;
    int i = idx >> 8;
    int j = idx & 255;
    const float* bh = (j < 128) ? bhf : bhb;
    int jj = j & 127;
    size_t base = (size_t)i * 768 + (j < 128 ? 0 : 384);
    float ir = gi[base + jj];
    float iz = gi[base + 128 + jj];
    float in = gi[base + 256 + jj];
    float r  = sigmoidf_(ir + bh[jj]);
    float z  = sigmoidf_(iz + bh[128 + jj]);
    float ng = tanhf(in + r * bh[256 + jj]);
    float h  = (1.f - z) * ng;
    __nv_bfloat16 hh = __float2bfloat16(h);
    Hhi[idx] = hh;
    Hlo[idx] = __float2bfloat16(h - __bfloat162float(hh));
}

// ---------------- elementwise prep ----------------
__global__ void cvt_split(const float* __restrict__ src,
                          __nv_bfloat16* __restrict__ hi, __nv_bfloat16* __restrict__ lo,
                          size_t n) {
    size_t i = (size_t)blockIdx.x * blockDim.x + threadIdx.x;
    if (i >= n) return;
    float v = src[i];
    __nv_bfloat16 h = __float2bfloat16(v);
    hi[i] = h;
    lo[i] = __float2bfloat16(v - __bfloat162float(h));
}

__global__ void transpose_split(const float* __restrict__ src,
                                __nv_bfloat16* __restrict__ hi, __nv_bfloat16* __restrict__ lo,
                                int R, int C) {
    int i = blockIdx.x * blockDim.x + threadIdx.x;
    if (i >= R * C) return;
    int r = i / C, c = i - r * C;
    float v = src[i];
    __nv_bfloat16 h = __float2bfloat16(v);
    hi[(size_t)c * R + r] = h;
    lo[(size_t)c * R + r] = __float2bfloat16(v - __bfloat162float(h));
}

__global__ void transpose_k(const float* __restrict__ src, float* __restrict__ dst,
                            int R, int C) {
    int i = blockIdx.x * blockDim.x + threadIdx.x;
    if (i < R * C) { int r = i / C, c = i % C; dst[c * R + r] = src[i]; }
}

// ---------------- GCN chain stencil ----------------
__device__ __forceinline__ float stencil_val(const float* xw, int i, int c, int C, int n) {
    float di = rsqrtf(1.f + (float)(i > 0) + (float)(i < n - 1));
    float acc = di * xw[(size_t)i * C + c];
    if (i > 0)     acc += rsqrtf(2.f + (float)(i - 1 > 0))     * xw[(size_t)(i - 1) * C + c];
    if (i < n - 1) acc += rsqrtf(2.f + (float)(i + 1 < n - 1)) * xw[(size_t)(i + 1) * C + c];
    return di * acc;
}

__global__ void gcn_stencil_split(const float* __restrict__ xw, const float* __restrict__ bias,
                                  __nv_bfloat16* __restrict__ hi, __nv_bfloat16* __restrict__ lo,
                                  int C, int n) {
    size_t idx = (size_t)blockIdx.x * blockDim.x + threadIdx.x;
    if (idx >= (size_t)n * C) return;
    int i = idx / C, c = idx - (size_t)i * C;
    float v = stencil_val(xw, i, c, C, n) + bias[c];
    __nv_bfloat16 h = __float2bfloat16(v);
    hi[idx] = h;
    lo[idx] = __float2bfloat16(v - __bfloat162float(h));
}

__global__ void gcn_stencil_f32(const float* __restrict__ xw, const float* __restrict__ bias,
                                float* __restrict__ out, int C, int n) {
    size_t idx = (size_t)blockIdx.x * blockDim.x + threadIdx.x;
    if (idx >= (size_t)n * C) return;
    int i = idx / C, c = idx - (size_t)i * C;
    out[idx] = stencil_val(xw, i, c, C, n) + bias[c];
}

// ---------------- small SIMT GEMM (final fc only) ----------------
#define BM 128
#define BN 64
#define BK 16
#define TMI 8
#define TNJ 4
__global__ void __launch_bounds__(256)
gemm_bt(const float* __restrict__ A, int lda, const float* __restrict__ Bt,
        const float* __restrict__ bias, float* __restrict__ C, int ldc,
        int M, int Nc, int K)
{
    __shared__ float As[BK][BM];
    __shared__ float Bs[BK][BN];
    int tid = threadIdx.x, tx = tid & 15, ty = tid >> 4;
    int mBase = blockIdx.y * BM, nBase = blockIdx.x * BN;
    float acc[TMI][TNJ];
#pragma unroll
    for (int i = 0; i < TMI; i++)
#pragma unroll
        for (int j = 0; j < TNJ; j++) acc[i][j] = 0.f;
    int la_row = tid >> 2, la_c4 = (tid & 3) * 4;
    for (int k0 = 0; k0 < K; k0 += BK) {
#pragma unroll
        for (int h = 0; h < 2; h++) {
            int row = la_row + h * 64;
            float4 v = *reinterpret_cast<const float4*>(A + (size_t)(mBase + row) * lda + k0 + la_c4);
            As[la_c4 + 0][row] = v.x; As[la_c4 + 1][row] = v.y;
            As[la_c4 + 2][row] = v.z; As[la_c4 + 3][row] = v.w;
        }
        {
            int n = nBase + la_row;
            float4 v = make_float4(0.f, 0.f, 0.f, 0.f);
            if (n < Nc) v = *reinterpret_cast<const float4*>(Bt + (size_t)n * K + k0 + la_c4);
            Bs[la_c4 + 0][la_row] = v.x; Bs[la_c4 + 1][la_row] = v.y;
            Bs[la_c4 + 2][la_row] = v.z; Bs[la_c4 + 3][la_row] = v.w;
        }
        __syncthreads();
#pragma unroll
        for (int k = 0; k < BK; k++) {
            float4 a0 = *reinterpret_cast<const float4*>(&As[k][ty * TMI]);
            float4 a1 = *reinterpret_cast<const float4*>(&As[k][ty * TMI + 4]);
            float4 b  = *reinterpret_cast<const float4*>(&Bs[k][tx * TNJ]);
            float am[TMI] = {a0.x, a0.y, a0.z, a0.w, a1.x, a1.y, a1.z, a1.w};
            float bn[TNJ] = {b.x, b.y, b.z, b.w};
#pragma unroll
            for (int i = 0; i < TMI; i++)
#pragma unroll
                for (int j = 0; j < TNJ; j++) acc[i][j] = fmaf(am[i], bn[j], acc[i][j]);
        }
        __syncthreads();
    }
#pragma unroll
    for (int i = 0; i < TMI; i++) {
        int m = mBase + ty * TMI + i;
#pragma unroll
        for (int j = 0; j < TNJ; j++) {
            int n = nBase + tx * TNJ + j;
            if (n < Nc) {
                float v = acc[i][j];
                if (bias) v += bias[n];
                C[(size_t)m * ldc + n] = v;
            }
        }
    }
}

// ---------------- launch ----------------
extern "C" void kernel_launch(void* const* d_in, const int* in_sizes, int n_in,
                              void* d_out, int out_size)
{
    const float* x       = (const float*)d_in[0];
    const float* w_ih_f1 = (const float*)d_in[1];
    const float* b_ih_f1 = (const float*)d_in[2];
    const float* b_hh_f1 = (const float*)d_in[3];
    const float* w_ih_b1 = (const float*)d_in[4];
    const float* b_ih_b1 = (const float*)d_in[5];
    const float* b_hh_b1 = (const float*)d_in[6];
    const float* w_ih_f2 = (const float*)d_in[7];
    const float* b_ih_f2 = (const float*)d_in[8];
    const float* b_hh_f2 = (const float*)d_in[9];
    const float* w_ih_b2 = (const float*)d_in[10];
    const float* b_ih_b2 = (const float*)d_in[11];
    const float* b_hh_b2 = (const float*)d_in[12];
    const float* w_g1    = (const float*)d_in[13];
    const float* b_g1    = (const float*)d_in[14];
    const float* w_g2    = (const float*)d_in[15];
    const float* b_g2    = (const float*)d_in[16];
    const float* w_fc    = (const float*)d_in[17];
    const float* b_fc    = (const float*)d_in[18];
    float* out = (float*)d_out;

    float *gi, *xw1, *xw2, *g2, *wfct;
    __nv_bfloat16 *xhi, *xlo, *h1hi, *h1lo, *h2hi, *h2lo, *g1hi, *g1lo;
    __nv_bfloat16 *w1fhi, *w1flo, *w1bhi, *w1blo, *w2fhi, *w2flo, *w2bhi, *w2blo;
    __nv_bfloat16 *wg1hi, *wg1lo, *wg2hi, *wg2lo;
    cudaGetSymbolAddress((void**)&gi, g_gi);
    cudaGetSymbolAddress((void**)&xhi, g_xhi);   cudaGetSymbolAddress((void**)&xlo, g_xlo);
    cudaGetSymbolAddress((void**)&h1hi, g_h1hi); cudaGetSymbolAddress((void**)&h1lo, g_h1lo);
    cudaGetSymbolAddress((void**)&h2hi, g_h2hi); cudaGetSymbolAddress((void**)&h2lo, g_h2lo);
    cudaGetSymbolAddress((void**)&g1hi, g_g1hi); cudaGetSymbolAddress((void**)&g1lo, g_g1lo);
    cudaGetSymbolAddress((void**)&w1fhi, g_w1fhi); cudaGetSymbolAddress((void**)&w1flo, g_w1flo);
    cudaGetSymbolAddress((void**)&w1bhi, g_w1bhi); cudaGetSymbolAddress((void**)&w1blo, g_w1blo);
    cudaGetSymbolAddress((void**)&w2fhi, g_w2fhi); cudaGetSymbolAddress((void**)&w2flo, g_w2flo);
    cudaGetSymbolAddress((void**)&w2bhi, g_w2bhi); cudaGetSymbolAddress((void**)&w2blo, g_w2blo);
    cudaGetSymbolAddress((void**)&wg1hi, g_wg1hi); cudaGetSymbolAddress((void**)&wg1lo, g_wg1lo);
    cudaGetSymbolAddress((void**)&wg2hi, g_wg2hi); cudaGetSymbolAddress((void**)&wg2lo, g_wg2lo);
    cudaGetSymbolAddress((void**)&xw1, g_xw1);   cudaGetSymbolAddress((void**)&xw2, g_xw2);
    cudaGetSymbolAddress((void**)&g2, g_g2);     cudaGetSymbolAddress((void**)&wfct, g_wfct);

    const int SMEM128 = 4 * (128 * 80 + 128 * 80);   // 81920
    const int SMEM64  = 4 * (128 * 80 + 64 * 80);    // 61440
    cudaFuncSetAttribute(gemm3<128>, cudaFuncAttributeMaxDynamicSharedMemorySize, SMEM128);
    cudaFuncSetAttribute(gemm3<64>,  cudaFuncAttributeMaxDynamicSharedMemorySize, SMEM64);

    dim3 blk(256);

    // prep: split planes
    cvt_split<<<((size_t)NN * 128 + 255) / 256, blk>>>(x, xhi, xlo, (size_t)NN * 128);
    cvt_split<<<(384 * 128 + 255) / 256, blk>>>(w_ih_f1, w1fhi, w1flo, 384 * 128);
    cvt_split<<<(384 * 128 + 255) / 256, blk>>>(w_ih_b1, w1bhi, w1blo, 384 * 128);
    cvt_split<<<(384 * 256 + 255) / 256, blk>>>(w_ih_f2, w2fhi, w2flo, 384 * 256);
    cvt_split<<<(384 * 256 + 255) / 256, blk>>>(w_ih_b2, w2bhi, w2blo, 384 * 256);
    transpose_split<<<(256 * 128 + 255) / 256, blk>>>(w_g1, wg1hi, wg1lo, 256, 128);
    transpose_split<<<(128 * 64 + 255) / 256, blk>>>(w_g2, wg2hi, wg2lo, 128, 64);
    transpose_k<<<(64 * 10 + 255) / 256, blk>>>(w_fc, wfct, 64, 10);

    // GRU layer 1 (K=128): gi[:, 0:384] fwd, gi[:, 384:768] bwd
    gemm3<128><<<dim3(NN / 128, 3), blk, SMEM128>>>(xhi, xlo, 128, w1fhi, w1flo, b_ih_f1, gi, 768);
    gemm3<128><<<dim3(NN / 128, 3), blk, SMEM128>>>(xhi, xlo, 128, w1bhi, w1blo, b_ih_b1, gi + 384, 768);
    gru_act_split<<<(NN * 256 + 255) / 256, blk>>>(gi, b_hh_f1, b_hh_b1, h1hi, h1lo, NN);

    // GRU layer 2 (K=256)
    gemm3<128><<<dim3(NN / 128, 3), blk, SMEM128>>>(h1hi, h1lo, 256, w2fhi, w2flo, b_ih_f2, gi, 768);
    gemm3<128><<<dim3(NN / 128, 3), blk, SMEM128>>>(h1hi, h1lo, 256, w2bhi, w2blo, b_ih_b2, gi + 384, 768);
    gru_act_split<<<(NN * 256 + 255) / 256, blk>>>(gi, b_hh_f2, b_hh_b2, h2hi, h2lo, NN);

    // GCN1: xw1 = h2 @ w_g1 (K=256, Nc=128); stencil -> g1 planes
    gemm3<128><<<dim3(NN / 128, 1), blk, SMEM128>>>(h2hi, h2lo, 256, wg1hi, wg1lo, nullptr, xw1, 128);
    gcn_stencil_split<<<((size_t)NN * 128 + 255) / 256, blk>>>(xw1, b_g1, g1hi, g1lo, 128, NN);

    // GCN2: xw2 = g1 @ w_g2 (K=128, Nc=64); stencil -> g2 fp32
    gemm3<64><<<dim3(NN / 128, 1), blk, SMEM64>>>(g1hi, g1lo, 128, wg2hi, wg2lo, nullptr, xw2, 64);
    gcn_stencil_f32<<<((size_t)NN * 64 + 255) / 256, blk>>>(xw2, b_g2, g2, 64, NN);

    // final fc
    gemm_bt<<<dim3(1, NN / BM), blk>>>(g2, 64, wfct, b_fc, out, 10, NN, 10, 64);
}

// round 5
// speedup vs baseline: 2.8696x; 1.7824x over previous
#include <cuda_runtime.h>
#include <cuda_fp16.h>
#include <math.h>
#include <stdint.h>

#define NN 131072

// ---------------- static device scratch ----------------
__device__ float  g_gi [(size_t)NN * 768];
__device__ __half g_xh [(size_t)NN * 128];
__device__ __half g_h1 [(size_t)NN * 256];
__device__ __half g_h2 [(size_t)NN * 256];
__device__ float  g_xw1[(size_t)NN * 128];
__device__ __half g_g1 [(size_t)NN * 128];
__device__ float  g_xw2[(size_t)NN * 64];
__device__ float  g_g2 [(size_t)NN * 64];
__device__ __half g_w1f[384 * 128], g_w1b[384 * 128];
__device__ __half g_w2f[384 * 256], g_w2b[384 * 256];
__device__ __half g_wg1[128 * 256];
__device__ __half g_wg2[64 * 128];
__device__ float  g_wfct[10 * 64];

// ---------------- PTX helpers (baseline PTX; works on generic compute_103) ----------------
__device__ __forceinline__ uint32_t smem_u32(const void* p) {
    uint32_t a;
    asm("{ .reg .u64 t; cvta.to.shared.u64 t, %1; cvt.u32.u64 %0, t; }" : "=r"(a) : "l"(p));
    return a;
}
__device__ __forceinline__ void cp16(uint32_t dst, const void* src) {
    asm volatile("cp.async.cg.shared.global [%0], [%1], 16;" :: "r"(dst), "l"(src));
}
__device__ __forceinline__ void cp_commit() {
    asm volatile("cp.async.commit_group;");
}
__device__ __forceinline__ void cp_wait2() {
    asm volatile("cp.async.wait_group 2;");
}
__device__ __forceinline__ void ldm_x4(uint32_t& r0, uint32_t& r1, uint32_t& r2, uint32_t& r3,
                                       uint32_t addr) {
    asm volatile("ldmatrix.sync.aligned.m8n8.x4.shared.b16 {%0,%1,%2,%3}, [%4];"
                 : "=r"(r0), "=r"(r1), "=r"(r2), "=r"(r3) : "r"(addr));
}
__device__ __forceinline__ void mma_f16(float* d, const uint32_t* a, const uint32_t* b) {
    asm volatile("mma.sync.aligned.m16n8k16.row.col.f32.f16.f16.f32 "
                 "{%0,%1,%2,%3}, {%4,%5,%6,%7}, {%8,%9}, {%0,%1,%2,%3};"
                 : "+f"(d[0]), "+f"(d[1]), "+f"(d[2]), "+f"(d[3])
                 : "r"(a[0]), "r"(a[1]), "r"(a[2]), "r"(a[3]), "r"(b[0]), "r"(b[1]));
}
__device__ __forceinline__ float sigmoidf_(float x) { return 1.f / (1.f + expf(-x)); }

// ---------------- fp16 MMA GEMM: C[M, cols] = A@B^T (+bias), fp32 out ----------------
// A [M,K] K-major fp16. B_d [colsTotal,K] K-major fp16, selected per direction.
// grid.y covers column tiles; dir = blockIdx.y / slicesPerDir selects (B,bias).
// CTA tile 128 x NT. 8 warps: wy in {0,1} (64 rows), wx in 0..3.
template <int NT>
__global__ void __launch_bounds__(256, 2)
gemm_h(const __half* __restrict__ A, int K,
       const __half* __restrict__ B0, const __half* __restrict__ B1,
       const float* __restrict__ bias0, const float* __restrict__ bias1,
       int slicesPerDir, float* __restrict__ C, int ldc)
{
    extern __shared__ char sm[];
    constexpr int AST = 80;                 // padded row stride (bytes) for 32 fp16
    constexpr int ABYTES = 128 * AST;       // 10240
    constexpr int BBYTES = NT * AST;
    constexpr int STAGE = ABYTES + BBYTES;
    constexpr int NJ = NT / 32;             // n8 tiles per warp

    const int tid = threadIdx.x, lane = tid & 31, wid = tid >> 5;
    const int wy = wid & 1, wx = wid >> 1;
    const int mBase = blockIdx.x * 128;
    const int dir = blockIdx.y / slicesPerDir;
    const int nBase = (blockIdx.y % slicesPerDir) * NT;   // into B / bias
    const int cBase = blockIdx.y * NT;                    // into C
    const __half* B = dir ? B1 : B0;
    const float* bias = dir ? bias1 : bias0;
    const int NCH = K >> 5;                 // 32-col chunks

    const uint32_t sbase = smem_u32(sm);
    const int arow = tid >> 1, acol = (tid & 1) * 2;
    const int brow64 = tid >> 2, bch64 = tid & 3;

    auto issue = [&](int c) {
        int kk = c * 32;
        uint32_t st = sbase + (c & 3) * STAGE;
        const __half* ga = A + (size_t)(mBase + arow) * K + kk + acol * 8;
        uint32_t da = st + arow * AST + acol * 16;
        cp16(da, ga);
        cp16(da + 16, ga + 8);
        if (NT == 128) {
            const __half* gb = B + (size_t)(nBase + arow) * K + kk + acol * 8;
            uint32_t db = st + ABYTES + arow * AST + acol * 16;
            cp16(db, gb);
            cp16(db + 16, gb + 8);
        } else {
            const __half* gb = B + (size_t)(nBase + brow64) * K + kk + bch64 * 8;
            cp16(st + ABYTES + brow64 * AST + bch64 * 16, gb);
        }
        cp_commit();
    };

    float acc[4][NJ][4];
#pragma unroll
    for (int i = 0; i < 4; i++)
#pragma unroll
        for (int j = 0; j < NJ; j++)
#pragma unroll
            for (int q = 0; q < 4; q++) acc[i][j][q] = 0.f;

    issue(0); issue(1); issue(2);

    const uint32_t a_lrow = (lane & 15), a_khalf = (lane >> 4) * 16;
    for (int c = 0; c < NCH; c++) {
        cp_wait2();
        __syncthreads();
        // exactly one commit per iteration (empty past the end) so wait_group 2
        // always guarantees chunk c is resident
        if (c + 3 < NCH) issue(c + 3);
        else cp_commit();
        uint32_t st = sbase + (c & 3) * STAGE;
#pragma unroll
        for (int kh = 0; kh < 2; kh++) {
            uint32_t a[4][4];
#pragma unroll
            for (int i = 0; i < 4; i++) {
                uint32_t addr = st + (wy * 64 + i * 16 + a_lrow) * AST + kh * 32 + a_khalf;
                ldm_x4(a[i][0], a[i][1], a[i][2], a[i][3], addr);
            }
            uint32_t bf[NJ][2];
#pragma unroll
            for (int jj = 0; jj < NJ / 2; jj++) {
                uint32_t r0, r1, r2, r3;
                uint32_t addr = st + ABYTES +
                    (wx * (NT / 4) + jj * 16 + a_lrow) * AST + kh * 32 + a_khalf;
                ldm_x4(r0, r1, r2, r3, addr);
                bf[2 * jj][0] = r0; bf[2 * jj][1] = r2;
                bf[2 * jj + 1][0] = r1; bf[2 * jj + 1][1] = r3;
            }
#pragma unroll
            for (int i = 0; i < 4; i++)
#pragma unroll
                for (int j = 0; j < NJ; j++)
                    mma_f16(acc[i][j], a[i], bf[j]);
        }
    }

    // epilogue
#pragma unroll
    for (int i = 0; i < 4; i++) {
        int r0 = mBase + wy * 64 + i * 16 + (lane >> 2);
#pragma unroll
        for (int j = 0; j < NJ; j++) {
            int ncol = wx * (NT / 4) + j * 8 + (lane & 3) * 2;
            float b0 = 0.f, b1 = 0.f;
            if (bias) { b0 = bias[nBase + ncol]; b1 = bias[nBase + ncol + 1]; }
            float2* p0 = (float2*)(C + (size_t)r0 * ldc + cBase + ncol);
            float2* p1 = (float2*)(C + (size_t)(r0 + 8) * ldc + cBase + ncol);
            *p0 = make_float2(acc[i][j][0] + b0, acc[i][j][1] + b1);
            *p1 = make_float2(acc[i][j][2] + b0, acc[i][j][3] + b1);
        }
    }
}

// ---------------- GRU gate activation -> fp16 ----------------
// gi per row: [f_r(128) f_z f_n | b_r b_z b_n] (768). H [N,256] fp16.
__global__ void gru_act_h(const float* __restrict__ gi,
                          const float* __restrict__ bhf,
                          const float* __restrict__ bhb,
                          __half* __restrict__ H, int n)
{
    int idx = blockIdx.x * blockDim.x + threadIdx.x;
    if (idx >= n * 256) return;
    int i = idx >> 8;
    int j = idx & 255;
    const float* bh = (j < 128) ? bhf : bhb;
    int jj = j & 127;
    size_t base = (size_t)i * 768 + (j < 128 ? 0 : 384);
    float ir = gi[base + jj];
    float iz = gi[base + 128 + jj];
    float in = gi[base + 256 + jj];
    float r  = sigmoidf_(ir + bh[jj]);
    float z  = sigmoidf_(iz + bh[128 + jj]);
    float ng = tanhf(in + r * bh[256 + jj]);
    H[idx] = __float2half_rn((1.f - z) * ng);
}

// ---------------- prep kernels ----------------
__global__ void cvt_h(const float* __restrict__ src, __half* __restrict__ dst, size_t n) {
    size_t i = (size_t)blockIdx.x * blockDim.x + threadIdx.x;
    if (i < n) dst[i] = __float2half_rn(src[i]);
}

__global__ void transpose_h(const float* __restrict__ src, __half* __restrict__ dst,
                            int R, int C) {
    int i = blockIdx.x * blockDim.x + threadIdx.x;
    if (i >= R * C) return;
    int r = i / C, c = i - r * C;
    dst[(size_t)c * R + r] = __float2half_rn(src[i]);
}

__global__ void transpose_k(const float* __restrict__ src, float* __restrict__ dst,
                            int R, int C) {
    int i = blockIdx.x * blockDim.x + threadIdx.x;
    if (i < R * C) { int r = i / C, c = i % C; dst[c * R + r] = src[i]; }
}

// ---------------- GCN chain stencil ----------------
__device__ __forceinline__ float stencil_val(const float* xw, int i, int c, int C, int n) {
    float di = rsqrtf(1.f + (float)(i > 0) + (float)(i < n - 1));
    float acc = di * xw[(size_t)i * C + c];
    if (i > 0)     acc += rsqrtf(2.f + (float)(i - 1 > 0))     * xw[(size_t)(i - 1) * C + c];
    if (i < n - 1) acc += rsqrtf(2.f + (float)(i + 1 < n - 1)) * xw[(size_t)(i + 1) * C + c];
    return di * acc;
}

__global__ void gcn_stencil_h(const float* __restrict__ xw, const float* __restrict__ bias,
                              __half* __restrict__ out, int C, int n) {
    size_t idx = (size_t)blockIdx.x * blockDim.x + threadIdx.x;
    if (idx >= (size_t)n * C) return;
    int i = idx / C, c = idx - (size_t)i * C;
    out[idx] = __float2half_rn(stencil_val(xw, i, c, C, n) + bias[c]);
}

__global__ void gcn_stencil_f32(const float* __restrict__ xw, const float* __restrict__ bias,
                                float* __restrict__ out, int C, int n) {
    size_t idx = (size_t)blockIdx.x * blockDim.x + threadIdx.x;
    if (idx >= (size_t)n * C) return;
    int i = idx / C, c = idx - (size_t)i * C;
    out[idx] = stencil_val(xw, i, c, C, n) + bias[c];
}

// ---------------- small SIMT GEMM (final fc only) ----------------
#define BM 128
#define BN 64
#define BK 16
#define TMI 8
#define TNJ 4
__global__ void __launch_bounds__(256)
gemm_bt(const float* __restrict__ A, int lda, const float* __restrict__ Bt,
        const float* __restrict__ bias, float* __restrict__ C, int ldc,
        int M, int Nc, int K)
{
    __shared__ float As[BK][BM];
    __shared__ float Bs[BK][BN];
    int tid = threadIdx.x, tx = tid & 15, ty = tid >> 4;
    int mBase = blockIdx.y * BM, nBase = blockIdx.x * BN;
    float acc[TMI][TNJ];
#pragma unroll
    for (int i = 0; i < TMI; i++)
#pragma unroll
        for (int j = 0; j < TNJ; j++) acc[i][j] = 0.f;
    int la_row = tid >> 2, la_c4 = (tid & 3) * 4;
    for (int k0 = 0; k0 < K; k0 += BK) {
#pragma unroll
        for (int h = 0; h < 2; h++) {
            int row = la_row + h * 64;
            float4 v = *reinterpret_cast<const float4*>(A + (size_t)(mBase + row) * lda + k0 + la_c4);
            As[la_c4 + 0][row] = v.x; As[la_c4 + 1][row] = v.y;
            As[la_c4 + 2][row] = v.z; As[la_c4 + 3][row] = v.w;
        }
        {
            int n = nBase + la_row;
            float4 v = make_float4(0.f, 0.f, 0.f, 0.f);
            if (n < Nc) v = *reinterpret_cast<const float4*>(Bt + (size_t)n * K + k0 + la_c4);
            Bs[la_c4 + 0][la_row] = v.x; Bs[la_c4 + 1][la_row] = v.y;
            Bs[la_c4 + 2][la_row] = v.z; Bs[la_c4 + 3][la_row] = v.w;
        }
        __syncthreads();
#pragma unroll
        for (int k = 0; k < BK; k++) {
            float4 a0 = *reinterpret_cast<const float4*>(&As[k][ty * TMI]);
            float4 a1 = *reinterpret_cast<const float4*>(&As[k][ty * TMI + 4]);
            float4 b  = *reinterpret_cast<const float4*>(&Bs[k][tx * TNJ]);
            float am[TMI] = {a0.x, a0.y, a0.z, a0.w, a1.x, a1.y, a1.z, a1.w};
            float bn[TNJ] = {b.x, b.y, b.z, b.w};
#pragma unroll
            for (int i = 0; i < TMI; i++)
#pragma unroll
                for (int j = 0; j < TNJ; j++) acc[i][j] = fmaf(am[i], bn[j], acc[i][j]);
        }
        __syncthreads();
    }
#pragma unroll
    for (int i = 0; i < TMI; i++) {
        int m = mBase + ty * TMI + i;
#pragma unroll
        for (int j = 0; j < TNJ; j++) {
            int n = nBase + tx * TNJ + j;
            if (n < Nc) {
                float v = acc[i][j];
                if (bias) v += bias[n];
                C[(size_t)m * ldc + n] = v;
            }
        }
    }
}

// ---------------- launch ----------------
extern "C" void kernel_launch(void* const* d_in, const int* in_sizes, int n_in,
                              void* d_out, int out_size)
{
    const float* x       = (const float*)d_in[0];
    const float* w_ih_f1 = (const float*)d_in[1];
    const float* b_ih_f1 = (const float*)d_in[2];
    const float* b_hh_f1 = (const float*)d_in[3];
    const float* w_ih_b1 = (const float*)d_in[4];
    const float* b_ih_b1 = (const float*)d_in[5];
    const float* b_hh_b1 = (const float*)d_in[6];
    const float* w_ih_f2 = (const float*)d_in[7];
    const float* b_ih_f2 = (const float*)d_in[8];
    const float* b_hh_f2 = (const float*)d_in[9];
    const float* w_ih_b2 = (const float*)d_in[10];
    const float* b_ih_b2 = (const float*)d_in[11];
    const float* b_hh_b2 = (const float*)d_in[12];
    const float* w_g1    = (const float*)d_in[13];
    const float* b_g1    = (const float*)d_in[14];
    const float* w_g2    = (const float*)d_in[15];
    const float* b_g2    = (const float*)d_in[16];
    const float* w_fc    = (const float*)d_in[17];
    const float* b_fc    = (const float*)d_in[18];
    float* out = (float*)d_out;

    float *gi, *xw1, *xw2, *g2, *wfct;
    __half *xh, *h1, *h2, *g1, *w1f, *w1b, *w2f, *w2b, *wg1, *wg2;
    cudaGetSymbolAddress((void**)&gi, g_gi);
    cudaGetSymbolAddress((void**)&xh, g_xh);
    cudaGetSymbolAddress((void**)&h1, g_h1);
    cudaGetSymbolAddress((void**)&h2, g_h2);
    cudaGetSymbolAddress((void**)&g1, g_g1);
    cudaGetSymbolAddress((void**)&w1f, g_w1f); cudaGetSymbolAddress((void**)&w1b, g_w1b);
    cudaGetSymbolAddress((void**)&w2f, g_w2f); cudaGetSymbolAddress((void**)&w2b, g_w2b);
    cudaGetSymbolAddress((void**)&wg1, g_wg1); cudaGetSymbolAddress((void**)&wg2, g_wg2);
    cudaGetSymbolAddress((void**)&xw1, g_xw1); cudaGetSymbolAddress((void**)&xw2, g_xw2);
    cudaGetSymbolAddress((void**)&g2, g_g2);   cudaGetSymbolAddress((void**)&wfct, g_wfct);

    const int SMEM128 = 4 * (128 * 80 + 128 * 80);   // 81920
    const int SMEM64  = 4 * (128 * 80 + 64 * 80);    // 61440
    cudaFuncSetAttribute(gemm_h<128>, cudaFuncAttributeMaxDynamicSharedMemorySize, SMEM128);
    cudaFuncSetAttribute(gemm_h<64>,  cudaFuncAttributeMaxDynamicSharedMemorySize, SMEM64);

    dim3 blk(256);

    // prep: fp16 conversions
    cvt_h<<<((size_t)NN * 128 + 255) / 256, blk>>>(x, xh, (size_t)NN * 128);
    cvt_h<<<(384 * 128 + 255) / 256, blk>>>(w_ih_f1, w1f, 384 * 128);
    cvt_h<<<(384 * 128 + 255) / 256, blk>>>(w_ih_b1, w1b, 384 * 128);
    cvt_h<<<(384 * 256 + 255) / 256, blk>>>(w_ih_f2, w2f, 384 * 256);
    cvt_h<<<(384 * 256 + 255) / 256, blk>>>(w_ih_b2, w2b, 384 * 256);
    transpose_h<<<(256 * 128 + 255) / 256, blk>>>(w_g1, wg1, 256, 128);
    transpose_h<<<(128 * 64 + 255) / 256, blk>>>(w_g2, wg2, 128, 64);
    transpose_k<<<(64 * 10 + 255) / 256, blk>>>(w_fc, wfct, 64, 10);

    // GRU layer 1 (K=128): both directions in one launch, gi cols [0:768)
    gemm_h<128><<<dim3(NN / 128, 6), blk, SMEM128>>>(
        xh, 128, w1f, w1b, b_ih_f1, b_ih_b1, 3, gi, 768);
    gru_act_h<<<(NN * 256 + 255) / 256, blk>>>(gi, b_hh_f1, b_hh_b1, h1, NN);

    // GRU layer 2 (K=256)
    gemm_h<128><<<dim3(NN / 128, 6), blk, SMEM128>>>(
        h1, 256, w2f, w2b, b_ih_f2, b_ih_b2, 3, gi, 768);
    gru_act_h<<<(NN * 256 + 255) / 256, blk>>>(gi, b_hh_f2, b_hh_b2, h2, NN);

    // GCN1: xw1 = h2 @ w_g1 (K=256, 128 cols); stencil -> g1 fp16
    gemm_h<128><<<dim3(NN / 128, 1), blk, SMEM128>>>(
        h2, 256, wg1, wg1, nullptr, nullptr, 1, xw1, 128);
    gcn_stencil_h<<<((size_t)NN * 128 + 255) / 256, blk>>>(xw1, b_g1, g1, 128, NN);

    // GCN2: xw2 = g1 @ w_g2 (K=128, 64 cols); stencil -> g2 fp32
    gemm_h<64><<<dim3(NN / 128, 1), blk, SMEM64>>>(
        g1, 128, wg2, wg2, nullptr, nullptr, 1, xw2, 64);
    gcn_stencil_f32<<<((size_t)NN * 64 + 255) / 256, blk>>>(xw2, b_g2, g2, 64, NN);

    // final fc
    gemm_bt<<<dim3(1, NN / BM), blk>>>(g2, 64, wfct, b_fc, out, 10, NN, 10, 64);
}

// round 6
// speedup vs baseline: 3.5624x; 1.2414x over previous
#include <cuda_runtime.h>
#include <cuda_fp16.h>
#include <math.h>
#include <stdint.h>

#define NN 131072

// ---------------- static device scratch ----------------
__device__ __half g_xh [(size_t)NN * 128];
__device__ __half g_h1 [(size_t)NN * 256];
__device__ __half g_h2 [(size_t)NN * 256];
__device__ float  g_xw1[(size_t)NN * 128];
__device__ __half g_g1 [(size_t)NN * 128];
__device__ float  g_xw2[(size_t)NN * 64];
__device__ float  g_g2 [(size_t)NN * 64];
__device__ __half g_w1f[384 * 128], g_w1b[384 * 128];   // permuted layout
__device__ __half g_w2f[384 * 256], g_w2b[384 * 256];   // permuted layout
__device__ __half g_wg1[128 * 256];
__device__ __half g_wg2[64 * 128];
__device__ float  g_wfct[10 * 64];

// ---------------- PTX helpers ----------------
__device__ __forceinline__ uint32_t smem_u32(const void* p) {
    uint32_t a;
    asm("{ .reg .u64 t; cvta.to.shared.u64 t, %1; cvt.u32.u64 %0, t; }" : "=r"(a) : "l"(p));
    return a;
}
__device__ __forceinline__ void cp16(uint32_t dst, const void* src) {
    asm volatile("cp.async.cg.shared.global [%0], [%1], 16;" :: "r"(dst), "l"(src));
}
__device__ __forceinline__ void cp_commit() {
    asm volatile("cp.async.commit_group;");
}
__device__ __forceinline__ void cp_wait2() {
    asm volatile("cp.async.wait_group 2;");
}
__device__ __forceinline__ void ldm_x4(uint32_t& r0, uint32_t& r1, uint32_t& r2, uint32_t& r3,
                                       uint32_t addr) {
    asm volatile("ldmatrix.sync.aligned.m8n8.x4.shared.b16 {%0,%1,%2,%3}, [%4];"
                 : "=r"(r0), "=r"(r1), "=r"(r2), "=r"(r3) : "r"(addr));
}
__device__ __forceinline__ void mma_f16(float* d, const uint32_t* a, const uint32_t* b) {
    asm volatile("mma.sync.aligned.m16n8k16.row.col.f32.f16.f16.f32 "
                 "{%0,%1,%2,%3}, {%4,%5,%6,%7}, {%8,%9}, {%0,%1,%2,%3};"
                 : "+f"(d[0]), "+f"(d[1]), "+f"(d[2]), "+f"(d[3])
                 : "r"(a[0]), "r"(a[1]), "r"(a[2]), "r"(a[3]), "r"(b[0]), "r"(b[1]));
}
__device__ __forceinline__ float sigmoidf_(float x) { return 1.f / (1.f + expf(-x)); }

// ================= fused GRU GEMM + gates =================
// A [NN,K] fp16 K-major. Wp [384,K] fp16 in PERMUTED row order:
//   orig row g*128+h  ->  new row (h>>5)*96 + g*32 + (h&31)
// CTA: 128 rows x 192 cols (= 2 hidden 32-blocks x {r,z,n}).
// grid.y: dir = y>>1 (selects Wp/bias), hb = y&1 (B row base hb*192).
// 512 threads / 16 warps: wy=wid&7 (16 rows), wx=wid>>3 (96 cols).
// Epilogue computes h = (1-z)*tanh(n + r*bhn) and writes fp16 H[row, dir*128+h].
__global__ void __launch_bounds__(512, 1)
gru_fused(const __half* __restrict__ A, int K,
          const __half* __restrict__ Wp0, const __half* __restrict__ Wp1,
          const float* __restrict__ bihf, const float* __restrict__ bihb,
          const float* __restrict__ bhhf, const float* __restrict__ bhhb,
          __half* __restrict__ H)
{
    extern __shared__ char sm[];
    constexpr int AST = 80;
    constexpr int ABYTES = 128 * AST;          // 10240
    constexpr int BBYTES = 192 * AST;          // 15360
    constexpr int STAGE = ABYTES + BBYTES;     // 25600
    constexpr int BIAS_OFF = 4 * STAGE;        // 102400

    const int tid = threadIdx.x, lane = tid & 31, wid = tid >> 5;
    const int wy = wid & 7, wx = wid >> 3;
    const int mBase = blockIdx.x * 128;
    const int dir = blockIdx.y >> 1;
    const int hb = blockIdx.y & 1;
    const __half* Wp = dir ? Wp1 : Wp0;
    const float* bih = dir ? bihb : bihf;
    const float* bhh = dir ? bhhb : bhhf;
    const int rowB = hb * 192;
    const int NCH = K >> 5;

    const uint32_t sbase = smem_u32(sm);
    float* s_bih = (float*)(sm + BIAS_OFF);
    float* s_bhh = s_bih + 384;
    for (int i = tid; i < 384; i += 512) { s_bih[i] = bih[i]; s_bhh[i] = bhh[i]; }

    const int arow = tid >> 2, acol = tid & 3;

    auto issue = [&](int c) {
        int kk = c * 32;
        uint32_t st = sbase + (c & 3) * STAGE;
        // A: 128 rows x 4 x 16B = 512 units (1 per thread)
        cp16(st + arow * AST + acol * 16,
             A + (size_t)(mBase + arow) * K + kk + acol * 8);
        // B: 192 rows x 4 = 768 units
        {
            int u = tid;
            cp16(st + ABYTES + (u >> 2) * AST + (u & 3) * 16,
                 Wp + (size_t)(rowB + (u >> 2)) * K + kk + (u & 3) * 8);
        }
        if (tid < 256) {
            int u = 512 + tid;
            cp16(st + ABYTES + (u >> 2) * AST + (u & 3) * 16,
                 Wp + (size_t)(rowB + (u >> 2)) * K + kk + (u & 3) * 8);
        }
        cp_commit();
    };

    float acc[12][4];
#pragma unroll
    for (int t = 0; t < 12; t++)
#pragma unroll
        for (int q = 0; q < 4; q++) acc[t][q] = 0.f;

    issue(0); issue(1); issue(2);

    const uint32_t a_lrow = lane & 15, a_khalf = (lane >> 4) * 16;
    for (int c = 0; c < NCH; c++) {
        cp_wait2();
        __syncthreads();
        if (c + 3 < NCH) issue(c + 3);
        else cp_commit();            // keep group count aligned (tail-race fix)
        uint32_t st = sbase + (c & 3) * STAGE;
#pragma unroll
        for (int kh = 0; kh < 2; kh++) {
            uint32_t a[4];
            ldm_x4(a[0], a[1], a[2], a[3],
                   st + (wy * 16 + a_lrow) * AST + kh * 32 + a_khalf);
            uint32_t bf[12][2];
#pragma unroll
            for (int jj = 0; jj < 6; jj++) {
                uint32_t r0, r1, r2, r3;
                ldm_x4(r0, r1, r2, r3,
                       st + ABYTES + (wx * 96 + jj * 16 + a_lrow) * AST + kh * 32 + a_khalf);
                bf[2 * jj][0] = r0; bf[2 * jj][1] = r2;
                bf[2 * jj + 1][0] = r1; bf[2 * jj + 1][1] = r3;
            }
#pragma unroll
            for (int t = 0; t < 12; t++)
                mma_f16(acc[t], a, bf[t]);
        }
        __syncthreads();
    }

    // ---- fused gate epilogue ----
    const int s = hb * 2 + wx;                 // hidden 32-block index (0..3)
#pragma unroll
    for (int t = 0; t < 4; t++) {
#pragma unroll
        for (int rp = 0; rp < 2; rp++) {
            int row = mBase + wy * 16 + (lane >> 2) + rp * 8;
            __half hv[2];
#pragma unroll
            for (int q = 0; q < 2; q++) {
                int h = s * 32 + t * 8 + (lane & 3) * 2 + q;
                float ir = acc[t][rp * 2 + q];
                float iz = acc[t + 4][rp * 2 + q];
                float in = acc[t + 8][rp * 2 + q];
                float r  = sigmoidf_(ir + s_bih[h] + s_bhh[h]);
                float z  = sigmoidf_(iz + s_bih[128 + h] + s_bhh[128 + h]);
                float ng = tanhf(in + s_bih[256 + h] + r * s_bhh[256 + h]);
                hv[q] = __float2half_rn((1.f - z) * ng);
            }
            *(__half2*)(H + (size_t)row * 256 + dir * 128 + s * 32 + t * 8 + (lane & 3) * 2) =
                *(__half2*)hv;
        }
    }
}

// ---------------- fp16 MMA GEMM (GCN layers): C[M, NT] fp32 ----------------
template <int NT>
__global__ void __launch_bounds__(256, 2)
gemm_h(const __half* __restrict__ A, int K,
       const __half* __restrict__ B, float* __restrict__ C)
{
    extern __shared__ char sm[];
    constexpr int AST = 80;
    constexpr int ABYTES = 128 * AST;
    constexpr int BBYTES = NT * AST;
    constexpr int STAGE = ABYTES + BBYTES;
    constexpr int NJ = NT / 32;

    const int tid = threadIdx.x, lane = tid & 31, wid = tid >> 5;
    const int wy = wid & 1, wx = wid >> 1;
    const int mBase = blockIdx.x * 128;
    const int NCH = K >> 5;

    const uint32_t sbase = smem_u32(sm);
    const int arow = tid >> 1, acol = (tid & 1) * 2;
    const int brow64 = tid >> 2, bch64 = tid & 3;

    auto issue = [&](int c) {
        int kk = c * 32;
        uint32_t st = sbase + (c & 3) * STAGE;
        const __half* ga = A + (size_t)(mBase + arow) * K + kk + acol * 8;
        uint32_t da = st + arow * AST + acol * 16;
        cp16(da, ga);
        cp16(da + 16, ga + 8);
        if (NT == 128) {
            const __half* gb = B + (size_t)arow * K + kk + acol * 8;
            uint32_t db = st + ABYTES + arow * AST + acol * 16;
            cp16(db, gb);
            cp16(db + 16, gb + 8);
        } else {
            const __half* gb = B + (size_t)brow64 * K + kk + bch64 * 8;
            cp16(st + ABYTES + brow64 * AST + bch64 * 16, gb);
        }
        cp_commit();
    };

    float acc[4][NJ][4];
#pragma unroll
    for (int i = 0; i < 4; i++)
#pragma unroll
        for (int j = 0; j < NJ; j++)
#pragma unroll
            for (int q = 0; q < 4; q++) acc[i][j][q] = 0.f;

    issue(0); issue(1); issue(2);

    const uint32_t a_lrow = lane & 15, a_khalf = (lane >> 4) * 16;
    for (int c = 0; c < NCH; c++) {
        cp_wait2();
        __syncthreads();
        if (c + 3 < NCH) issue(c + 3);
        else cp_commit();
        uint32_t st = sbase + (c & 3) * STAGE;
#pragma unroll
        for (int kh = 0; kh < 2; kh++) {
            uint32_t a[4][4];
#pragma unroll
            for (int i = 0; i < 4; i++)
                ldm_x4(a[i][0], a[i][1], a[i][2], a[i][3],
                       st + (wy * 64 + i * 16 + a_lrow) * AST + kh * 32 + a_khalf);
            uint32_t bf[NJ][2];
#pragma unroll
            for (int jj = 0; jj < NJ / 2; jj++) {
                uint32_t r0, r1, r2, r3;
                ldm_x4(r0, r1, r2, r3,
                       st + ABYTES + (wx * (NT / 4) + jj * 16 + a_lrow) * AST + kh * 32 + a_khalf);
                bf[2 * jj][0] = r0; bf[2 * jj][1] = r2;
                bf[2 * jj + 1][0] = r1; bf[2 * jj + 1][1] = r3;
            }
#pragma unroll
            for (int i = 0; i < 4; i++)
#pragma unroll
                for (int j = 0; j < NJ; j++)
                    mma_f16(acc[i][j], a[i], bf[j]);
        }
        __syncthreads();
    }

#pragma unroll
    for (int i = 0; i < 4; i++) {
        int r0 = mBase + wy * 64 + i * 16 + (lane >> 2);
#pragma unroll
        for (int j = 0; j < NJ; j++) {
            int ncol = wx * (NT / 4) + j * 8 + (lane & 3) * 2;
            float2* p0 = (float2*)(C + (size_t)r0 * NT + ncol);
            float2* p1 = (float2*)(C + (size_t)(r0 + 8) * NT + ncol);
            *p0 = make_float2(acc[i][j][0], acc[i][j][1]);
            *p1 = make_float2(acc[i][j][2], acc[i][j][3]);
        }
    }
}

// ---------------- prep kernels ----------------
__global__ void cvt_h(const float* __restrict__ src, __half* __restrict__ dst, size_t n) {
    size_t i = (size_t)blockIdx.x * blockDim.x + threadIdx.x;
    if (i < n) dst[i] = __float2half_rn(src[i]);
}

// permuted GRU weight: orig row g*128+h -> new row (h>>5)*96 + g*32 + (h&31)
__global__ void w_prep(const float* __restrict__ w, __half* __restrict__ wp, int K) {
    int i = blockIdx.x * blockDim.x + threadIdx.x;
    if (i >= 384 * K) return;
    int p = i / K, k = i - p * K;
    int g = p >> 7, h = p & 127;
    int nr = (h >> 5) * 96 + g * 32 + (h & 31);
    wp[(size_t)nr * K + k] = __float2half_rn(w[i]);
}

__global__ void transpose_h(const float* __restrict__ src, __half* __restrict__ dst,
                            int R, int C) {
    int i = blockIdx.x * blockDim.x + threadIdx.x;
    if (i >= R * C) return;
    int r = i / C, c = i - r * C;
    dst[(size_t)c * R + r] = __float2half_rn(src[i]);
}

__global__ void transpose_k(const float* __restrict__ src, float* __restrict__ dst,
                            int R, int C) {
    int i = blockIdx.x * blockDim.x + threadIdx.x;
    if (i < R * C) { int r = i / C, c = i % C; dst[c * R + r] = src[i]; }
}

// ---------------- GCN chain stencil ----------------
__device__ __forceinline__ float stencil_val(const float* xw, int i, int c, int C, int n) {
    float di = rsqrtf(1.f + (float)(i > 0) + (float)(i < n - 1));
    float acc = di * xw[(size_t)i * C + c];
    if (i > 0)     acc += rsqrtf(2.f + (float)(i - 1 > 0))     * xw[(size_t)(i - 1) * C + c];
    if (i < n - 1) acc += rsqrtf(2.f + (float)(i + 1 < n - 1)) * xw[(size_t)(i + 1) * C + c];
    return di * acc;
}

__global__ void gcn_stencil_h(const float* __restrict__ xw, const float* __restrict__ bias,
                              __half* __restrict__ out, int C, int n) {
    size_t idx = (size_t)blockIdx.x * blockDim.x + threadIdx.x;
    if (idx >= (size_t)n * C) return;
    int i = idx / C, c = idx - (size_t)i * C;
    out[idx] = __float2half_rn(stencil_val(xw, i, c, C, n) + bias[c]);
}

__global__ void gcn_stencil_f32(const float* __restrict__ xw, const float* __restrict__ bias,
                                float* __restrict__ out, int C, int n) {
    size_t idx = (size_t)blockIdx.x * blockDim.x + threadIdx.x;
    if (idx >= (size_t)n * C) return;
    int i = idx / C, c = idx - (size_t)i * C;
    out[idx] = stencil_val(xw, i, c, C, n) + bias[c];
}

// ---------------- small SIMT GEMM (final fc only) ----------------
#define BM 128
#define BN 64
#define BK 16
#define TMI 8
#define TNJ 4
__global__ void __launch_bounds__(256)
gemm_bt(const float* __restrict__ A, int lda, const float* __restrict__ Bt,
        const float* __restrict__ bias, float* __restrict__ C, int ldc,
        int M, int Nc, int K)
{
    __shared__ float As[BK][BM];
    __shared__ float Bs[BK][BN];
    int tid = threadIdx.x, tx = tid & 15, ty = tid >> 4;
    int mBase = blockIdx.y * BM, nBase = blockIdx.x * BN;
    float acc[TMI][TNJ];
#pragma unroll
    for (int i = 0; i < TMI; i++)
#pragma unroll
        for (int j = 0; j < TNJ; j++) acc[i][j] = 0.f;
    int la_row = tid >> 2, la_c4 = (tid & 3) * 4;
    for (int k0 = 0; k0 < K; k0 += BK) {
#pragma unroll
        for (int h = 0; h < 2; h++) {
            int row = la_row + h * 64;
            float4 v = *reinterpret_cast<const float4*>(A + (size_t)(mBase + row) * lda + k0 + la_c4);
            As[la_c4 + 0][row] = v.x; As[la_c4 + 1][row] = v.y;
            As[la_c4 + 2][row] = v.z; As[la_c4 + 3][row] = v.w;
        }
        {
            int n = nBase + la_row;
            float4 v = make_float4(0.f, 0.f, 0.f, 0.f);
            if (n < Nc) v = *reinterpret_cast<const float4*>(Bt + (size_t)n * K + k0 + la_c4);
            Bs[la_c4 + 0][la_row] = v.x; Bs[la_c4 + 1][la_row] = v.y;
            Bs[la_c4 + 2][la_row] = v.z; Bs[la_c4 + 3][la_row] = v.w;
        }
        __syncthreads();
#pragma unroll
        for (int k = 0; k < BK; k++) {
            float4 a0 = *reinterpret_cast<const float4*>(&As[k][ty * TMI]);
            float4 a1 = *reinterpret_cast<const float4*>(&As[k][ty * TMI + 4]);
            float4 b  = *reinterpret_cast<const float4*>(&Bs[k][tx * TNJ]);
            float am[TMI] = {a0.x, a0.y, a0.z, a0.w, a1.x, a1.y, a1.z, a1.w};
            float bn[TNJ] = {b.x, b.y, b.z, b.w};
#pragma unroll
            for (int i = 0; i < TMI; i++)
#pragma unroll
                for (int j = 0; j < TNJ; j++) acc[i][j] = fmaf(am[i], bn[j], acc[i][j]);
        }
        __syncthreads();
    }
#pragma unroll
    for (int i = 0; i < TMI; i++) {
        int m = mBase + ty * TMI + i;
#pragma unroll
        for (int j = 0; j < TNJ; j++) {
            int n = nBase + tx * TNJ + j;
            if (n < Nc) {
                float v = acc[i][j];
                if (bias) v += bias[n];
                C[(size_t)m * ldc + n] = v;
            }
        }
    }
}

// ---------------- launch ----------------
extern "C" void kernel_launch(void* const* d_in, const int* in_sizes, int n_in,
                              void* d_out, int out_size)
{
    const float* x       = (const float*)d_in[0];
    const float* w_ih_f1 = (const float*)d_in[1];
    const float* b_ih_f1 = (const float*)d_in[2];
    const float* b_hh_f1 = (const float*)d_in[3];
    const float* w_ih_b1 = (const float*)d_in[4];
    const float* b_ih_b1 = (const float*)d_in[5];
    const float* b_hh_b1 = (const float*)d_in[6];
    const float* w_ih_f2 = (const float*)d_in[7];
    const float* b_ih_f2 = (const float*)d_in[8];
    const float* b_hh_f2 = (const float*)d_in[9];
    const float* w_ih_b2 = (const float*)d_in[10];
    const float* b_ih_b2 = (const float*)d_in[11];
    const float* b_hh_b2 = (const float*)d_in[12];
    const float* w_g1    = (const float*)d_in[13];
    const float* b_g1    = (const float*)d_in[14];
    const float* w_g2    = (const float*)d_in[15];
    const float* b_g2    = (const float*)d_in[16];
    const float* w_fc    = (const float*)d_in[17];
    const float* b_fc    = (const float*)d_in[18];
    float* out = (float*)d_out;

    float *xw1, *xw2, *g2, *wfct;
    __half *xh, *h1, *h2, *g1, *w1f, *w1b, *w2f, *w2b, *wg1, *wg2;
    cudaGetSymbolAddress((void**)&xh, g_xh);
    cudaGetSymbolAddress((void**)&h1, g_h1);
    cudaGetSymbolAddress((void**)&h2, g_h2);
    cudaGetSymbolAddress((void**)&g1, g_g1);
    cudaGetSymbolAddress((void**)&w1f, g_w1f); cudaGetSymbolAddress((void**)&w1b, g_w1b);
    cudaGetSymbolAddress((void**)&w2f, g_w2f); cudaGetSymbolAddress((void**)&w2b, g_w2b);
    cudaGetSymbolAddress((void**)&wg1, g_wg1); cudaGetSymbolAddress((void**)&wg2, g_wg2);
    cudaGetSymbolAddress((void**)&xw1, g_xw1); cudaGetSymbolAddress((void**)&xw2, g_xw2);
    cudaGetSymbolAddress((void**)&g2, g_g2);   cudaGetSymbolAddress((void**)&wfct, g_wfct);

    const int GRU_SMEM = 4 * 25600 + 2 * 384 * 4;    // 105472
    const int SMEM128 = 4 * (128 * 80 + 128 * 80);   // 81920
    const int SMEM64  = 4 * (128 * 80 + 64 * 80);    // 61440
    cudaFuncSetAttribute(gru_fused, cudaFuncAttributeMaxDynamicSharedMemorySize, GRU_SMEM);
    cudaFuncSetAttribute(gemm_h<128>, cudaFuncAttributeMaxDynamicSharedMemorySize, SMEM128);
    cudaFuncSetAttribute(gemm_h<64>,  cudaFuncAttributeMaxDynamicSharedMemorySize, SMEM64);

    dim3 blk(256);

    // prep
    cvt_h<<<((size_t)NN * 128 + 255) / 256, blk>>>(x, xh, (size_t)NN * 128);
    w_prep<<<(384 * 128 + 255) / 256, blk>>>(w_ih_f1, w1f, 128);
    w_prep<<<(384 * 128 + 255) / 256, blk>>>(w_ih_b1, w1b, 128);
    w_prep<<<(384 * 256 + 255) / 256, blk>>>(w_ih_f2, w2f, 256);
    w_prep<<<(384 * 256 + 255) / 256, blk>>>(w_ih_b2, w2b, 256);
    transpose_h<<<(256 * 128 + 255) / 256, blk>>>(w_g1, wg1, 256, 128);
    transpose_h<<<(128 * 64 + 255) / 256, blk>>>(w_g2, wg2, 128, 64);
    transpose_k<<<(64 * 10 + 255) / 256, blk>>>(w_fc, wfct, 64, 10);

    // GRU layer 1 (K=128): fused GEMM+gates -> h1 fp16
    gru_fused<<<dim3(NN / 128, 4), 512, GRU_SMEM>>>(
        xh, 128, w1f, w1b, b_ih_f1, b_ih_b1, b_hh_f1, b_hh_b1, h1);

    // GRU layer 2 (K=256): -> h2 fp16
    gru_fused<<<dim3(NN / 128, 4), 512, GRU_SMEM>>>(
        h1, 256, w2f, w2b, b_ih_f2, b_ih_b2, b_hh_f2, b_hh_b2, h2);

    // GCN1: xw1 = h2 @ w_g1 (K=256, 128 cols); stencil -> g1 fp16
    gemm_h<128><<<dim3(NN / 128, 1), blk, SMEM128>>>(h2, 256, wg1, xw1);
    gcn_stencil_h<<<((size_t)NN * 128 + 255) / 256, blk>>>(xw1, b_g1, g1, 128, NN);

    // GCN2: xw2 = g1 @ w_g2 (K=128, 64 cols); stencil -> g2 fp32
    gemm_h<64><<<dim3(NN / 128, 1), blk, SMEM64>>>(g1, 128, wg2, xw2);
    gcn_stencil_f32<<<((size_t)NN * 64 + 255) / 256, blk>>>(xw2, b_g2, g2, 64, NN);

    // final fc
    gemm_bt<<<dim3(1, NN / BM), blk>>>(g2, 64, wfct, b_fc, out, 10, NN, 10, 64);
}

// round 7
// speedup vs baseline: 3.6345x; 1.0203x over previous
#include <cuda_runtime.h>
#include <cuda_fp16.h>
#include <math.h>
#include <stdint.h>

#define NN 131072

// ---------------- static device scratch ----------------
__device__ __half g_xh [(size_t)NN * 128];
__device__ __half g_h1 [(size_t)NN * 256];
__device__ __half g_h2 [(size_t)NN * 256];
__device__ __half g_w1f[384 * 128], g_w1b[384 * 128];   // permuted layout
__device__ __half g_w2f[384 * 256], g_w2b[384 * 256];   // permuted layout
__device__ float  g_wbig[256 * 10];
__device__ float  g_bvec[10];
__device__ float  g_bc[10];

// ---------------- PTX helpers ----------------
__device__ __forceinline__ uint32_t smem_u32(const void* p) {
    uint32_t a;
    asm("{ .reg .u64 t; cvta.to.shared.u64 t, %1; cvt.u32.u64 %0, t; }" : "=r"(a) : "l"(p));
    return a;
}
__device__ __forceinline__ void cp16(uint32_t dst, const void* src) {
    asm volatile("cp.async.cg.shared.global [%0], [%1], 16;" :: "r"(dst), "l"(src));
}
__device__ __forceinline__ void cp_commit() {
    asm volatile("cp.async.commit_group;");
}
__device__ __forceinline__ void cp_wait2() {
    asm volatile("cp.async.wait_group 2;");
}
__device__ __forceinline__ void ldm_x4(uint32_t& r0, uint32_t& r1, uint32_t& r2, uint32_t& r3,
                                       uint32_t addr) {
    asm volatile("ldmatrix.sync.aligned.m8n8.x4.shared.b16 {%0,%1,%2,%3}, [%4];"
                 : "=r"(r0), "=r"(r1), "=r"(r2), "=r"(r3) : "r"(addr));
}
__device__ __forceinline__ void mma_f16(float* d, const uint32_t* a, const uint32_t* b) {
    asm volatile("mma.sync.aligned.m16n8k16.row.col.f32.f16.f16.f32 "
                 "{%0,%1,%2,%3}, {%4,%5,%6,%7}, {%8,%9}, {%0,%1,%2,%3};"
                 : "+f"(d[0]), "+f"(d[1]), "+f"(d[2]), "+f"(d[3])
                 : "r"(a[0]), "r"(a[1]), "r"(a[2]), "r"(a[3]), "r"(b[0]), "r"(b[1]));
}
__device__ __forceinline__ float sigmoidf_(float x) { return 1.f / (1.f + expf(-x)); }

// ================= fused GRU GEMM + gates =================
// A [NN,K] fp16 K-major. Wp [384,K] fp16 in PERMUTED row order:
//   orig row g*128+h  ->  new row (h>>5)*96 + g*32 + (h&31)
// CTA: 128 rows x 192 cols (= 2 hidden 32-blocks x {r,z,n}).
// grid.y: dir = y>>1 (selects Wp/bias), hb = y&1 (B row base hb*192).
// 512 threads / 16 warps: wy=wid&7 (16 rows), wx=wid>>3 (96 cols).
__global__ void __launch_bounds__(512, 1)
gru_fused(const __half* __restrict__ A, int K,
          const __half* __restrict__ Wp0, const __half* __restrict__ Wp1,
          const float* __restrict__ bihf, const float* __restrict__ bihb,
          const float* __restrict__ bhhf, const float* __restrict__ bhhb,
          __half* __restrict__ H)
{
    extern __shared__ char sm[];
    constexpr int AST = 80;
    constexpr int ABYTES = 128 * AST;          // 10240
    constexpr int BBYTES = 192 * AST;          // 15360
    constexpr int STAGE = ABYTES + BBYTES;     // 25600
    constexpr int BIAS_OFF = 4 * STAGE;        // 102400

    const int tid = threadIdx.x, lane = tid & 31, wid = tid >> 5;
    const int wy = wid & 7, wx = wid >> 3;
    const int mBase = blockIdx.x * 128;
    const int dir = blockIdx.y >> 1;
    const int hb = blockIdx.y & 1;
    const __half* Wp = dir ? Wp1 : Wp0;
    const float* bih = dir ? bihb : bihf;
    const float* bhh = dir ? bhhb : bhhf;
    const int rowB = hb * 192;
    const int NCH = K >> 5;

    const uint32_t sbase = smem_u32(sm);
    float* s_bih = (float*)(sm + BIAS_OFF);
    float* s_bhh = s_bih + 384;
    for (int i = tid; i < 384; i += 512) { s_bih[i] = bih[i]; s_bhh[i] = bhh[i]; }

    const int arow = tid >> 2, acol = tid & 3;

    auto issue = [&](int c) {
        int kk = c * 32;
        uint32_t st = sbase + (c & 3) * STAGE;
        cp16(st + arow * AST + acol * 16,
             A + (size_t)(mBase + arow) * K + kk + acol * 8);
        {
            int u = tid;
            cp16(st + ABYTES + (u >> 2) * AST + (u & 3) * 16,
                 Wp + (size_t)(rowB + (u >> 2)) * K + kk + (u & 3) * 8);
        }
        if (tid < 256) {
            int u = 512 + tid;
            cp16(st + ABYTES + (u >> 2) * AST + (u & 3) * 16,
                 Wp + (size_t)(rowB + (u >> 2)) * K + kk + (u & 3) * 8);
        }
        cp_commit();
    };

    float acc[12][4];
#pragma unroll
    for (int t = 0; t < 12; t++)
#pragma unroll
        for (int q = 0; q < 4; q++) acc[t][q] = 0.f;

    issue(0); issue(1); issue(2);

    const uint32_t a_lrow = lane & 15, a_khalf = (lane >> 4) * 16;
    for (int c = 0; c < NCH; c++) {
        cp_wait2();
        __syncthreads();   // also orders prior-iteration ldsm before stage reuse
        if (c + 3 < NCH) issue(c + 3);
        else cp_commit();  // keep group count aligned (tail-race fix)
        uint32_t st = sbase + (c & 3) * STAGE;
#pragma unroll
        for (int kh = 0; kh < 2; kh++) {
            uint32_t a[4];
            ldm_x4(a[0], a[1], a[2], a[3],
                   st + (wy * 16 + a_lrow) * AST + kh * 32 + a_khalf);
            uint32_t bf[12][2];
#pragma unroll
            for (int jj = 0; jj < 6; jj++) {
                uint32_t r0, r1, r2, r3;
                ldm_x4(r0, r1, r2, r3,
                       st + ABYTES + (wx * 96 + jj * 16 + a_lrow) * AST + kh * 32 + a_khalf);
                bf[2 * jj][0] = r0; bf[2 * jj][1] = r2;
                bf[2 * jj + 1][0] = r1; bf[2 * jj + 1][1] = r3;
            }
#pragma unroll
            for (int t = 0; t < 12; t++)
                mma_f16(acc[t], a, bf[t]);
        }
    }

    // ---- fused gate epilogue ----
    const int s = hb * 2 + wx;                 // hidden 32-block index (0..3)
#pragma unroll
    for (int t = 0; t < 4; t++) {
#pragma unroll
        for (int rp = 0; rp < 2; rp++) {
            int row = mBase + wy * 16 + (lane >> 2) + rp * 8;
            __half hv[2];
#pragma unroll
            for (int q = 0; q < 2; q++) {
                int h = s * 32 + t * 8 + (lane & 3) * 2 + q;
                float ir = acc[t][rp * 2 + q];
                float iz = acc[t + 4][rp * 2 + q];
                float in = acc[t + 8][rp * 2 + q];
                float r  = sigmoidf_(ir + s_bih[h] + s_bhh[h]);
                float z  = sigmoidf_(iz + s_bih[128 + h] + s_bhh[128 + h]);
                float ng = tanhf(in + s_bih[256 + h] + r * s_bhh[256 + h]);
                hv[q] = __float2half_rn((1.f - z) * ng);
            }
            *(__half2*)(H + (size_t)row * 256 + dir * 128 + s * 32 + t * 8 + (lane & 3) * 2) =
                *(__half2*)hv;
        }
    }
}

// ---------------- prep kernels ----------------
__global__ void cvt_h(const float* __restrict__ src, __half* __restrict__ dst, size_t n) {
    size_t i = (size_t)blockIdx.x * blockDim.x + threadIdx.x;
    if (i < n) dst[i] = __float2half_rn(src[i]);
}

// permuted GRU weight: orig row g*128+h -> new row (h>>5)*96 + g*32 + (h&31)
__global__ void w_prep(const float* __restrict__ w, __half* __restrict__ wp, int K) {
    int i = blockIdx.x * blockDim.x + threadIdx.x;
    if (i >= 384 * K) return;
    int p = i / K, k = i - p * K;
    int g = p >> 7, h = p & 127;
    int nr = (h >> 5) * 96 + g * 32 + (h & 31);
    wp[(size_t)nr * K + k] = __float2half_rn(w[i]);
}

// Wbig = Wg1 @ (Wg2 @ Wfc)  [256,10];  bvec = bg1 @ (Wg2@Wfc);  bc = bg2@Wfc + bfc
__global__ void wbig_prep(const float* __restrict__ wg1, const float* __restrict__ bg1,
                          const float* __restrict__ wg2, const float* __restrict__ bg2,
                          const float* __restrict__ wfc, const float* __restrict__ bfc,
                          float* __restrict__ Wbig, float* __restrict__ bvec,
                          float* __restrict__ bc)
{
    __shared__ float t1[1280];            // [128,10] = wg2 @ wfc
    int tid = threadIdx.x;
    for (int i = tid; i < 1280; i += 256) {
        int j = i / 10, c = i - j * 10;
        float s = 0.f;
        for (int m = 0; m < 64; m++) s += wg2[j * 64 + m] * wfc[m * 10 + c];
        t1[i] = s;
    }
    __syncthreads();
    for (int i = tid; i < 2560; i += 256) {
        int j = i / 10, c = i - j * 10;
        float s = 0.f;
        for (int k = 0; k < 128; k++) s += wg1[j * 128 + k] * t1[k * 10 + c];
        Wbig[i] = s;
    }
    if (tid < 10) {
        float s = 0.f;
        for (int k = 0; k < 128; k++) s += bg1[k] * t1[k * 10 + tid];
        bvec[tid] = s;
        float s2 = 0.f;
        for (int m = 0; m < 64; m++) s2 += bg2[m] * wfc[m * 10 + tid];
        bc[tid] = s2 + bfc[tid];
    }
}

// ================= fused S^2 stencil + final projection =================
// out[i,:] = S^2(h2)[i,:] @ Wbig + s_i*bvec + bc
// S(x)[i] = d_i * (d_{i-1} x_{i-1} + d_i x_i + d_{i+1} x_{i+1}),  d_j = deg_j^{-1/2}
// 5-point closed form; one thread per node row.
__global__ void __launch_bounds__(256)
fc_final(const __half* __restrict__ h2, const float* __restrict__ Wbig,
         const float* __restrict__ bvec, const float* __restrict__ bc,
         float* __restrict__ out, int n)
{
    __shared__ float sW[2560];
    __shared__ float sbv[10], sbc[10];
    int tid = threadIdx.x;
    for (int i = tid; i < 2560; i += 256) sW[i] = Wbig[i];
    if (tid < 10) { sbv[tid] = bvec[tid]; sbc[tid] = bc[tid]; }
    __syncthreads();

    int i = blockIdx.x * 256 + tid;
    if (i >= n) return;

    auto dfun = [n](int j) -> float {
        if (j < 0 || j >= n) return 0.f;
        return rsqrtf(1.f + (float)(j > 0) + (float)(j < n - 1));
    };
    float dm2 = dfun(i - 2), dm1 = dfun(i - 1), d0 = dfun(i);
    float dp1 = dfun(i + 1), dp2 = dfun(i + 2);
    float w0 = d0 * dm2 * dm1 * dm1;
    float w1 = d0 * dm1 * (dm1 * dm1 + d0 * d0);
    float w2 = d0 * d0 * (dm1 * dm1 + d0 * d0 + dp1 * dp1);
    float w3 = d0 * dp1 * (dp1 * dp1 + d0 * d0);
    float w4 = d0 * dp2 * dp1 * dp1;
    float si = d0 * (dm1 + d0 + dp1);

    float acc[10];
#pragma unroll
    for (int c = 0; c < 10; c++) acc[c] = si * sbv[c] + sbc[c];

    int j0 = max(i - 2, 0), j1 = max(i - 1, 0);
    int j3 = min(i + 1, n - 1), j4 = min(i + 2, n - 1);
    const uint4* r0 = (const uint4*)(h2 + (size_t)j0 * 256);
    const uint4* r1 = (const uint4*)(h2 + (size_t)j1 * 256);
    const uint4* r2 = (const uint4*)(h2 + (size_t)i  * 256);
    const uint4* r3 = (const uint4*)(h2 + (size_t)j3 * 256);
    const uint4* r4 = (const uint4*)(h2 + (size_t)j4 * 256);

    for (int kb = 0; kb < 32; kb++) {
        uint4 q0 = r0[kb], q1 = r1[kb], q2 = r2[kb], q3 = r3[kb], q4 = r4[kb];
#pragma unroll
        for (int u = 0; u < 4; u++) {
            float2 f0 = __half22float2(((const __half2*)&q0)[u]);
            float2 f1 = __half22float2(((const __half2*)&q1)[u]);
            float2 f2 = __half22float2(((const __half2*)&q2)[u]);
            float2 f3 = __half22float2(((const __half2*)&q3)[u]);
            float2 f4 = __half22float2(((const __half2*)&q4)[u]);
            float zx = w0 * f0.x + w1 * f1.x + w2 * f2.x + w3 * f3.x + w4 * f4.x;
            float zy = w0 * f0.y + w1 * f1.y + w2 * f2.y + w3 * f3.y + w4 * f4.y;
            int kcol = kb * 8 + u * 2;
            const float* wA = &sW[kcol * 10];
            const float* wB = &sW[(kcol + 1) * 10];
#pragma unroll
            for (int c = 0; c < 10; c++)
                acc[c] += zx * wA[c] + zy * wB[c];
        }
    }
#pragma unroll
    for (int c = 0; c < 10; c++)
        out[(size_t)i * 10 + c] = acc[c];
}

// ---------------- launch ----------------
extern "C" void kernel_launch(void* const* d_in, const int* in_sizes, int n_in,
                              void* d_out, int out_size)
{
    const float* x       = (const float*)d_in[0];
    const float* w_ih_f1 = (const float*)d_in[1];
    const float* b_ih_f1 = (const float*)d_in[2];
    const float* b_hh_f1 = (const float*)d_in[3];
    const float* w_ih_b1 = (const float*)d_in[4];
    const float* b_ih_b1 = (const float*)d_in[5];
    const float* b_hh_b1 = (const float*)d_in[6];
    const float* w_ih_f2 = (const float*)d_in[7];
    const float* b_ih_f2 = (const float*)d_in[8];
    const float* b_hh_f2 = (const float*)d_in[9];
    const float* w_ih_b2 = (const float*)d_in[10];
    const float* b_ih_b2 = (const float*)d_in[11];
    const float* b_hh_b2 = (const float*)d_in[12];
    const float* w_g1    = (const float*)d_in[13];
    const float* b_g1    = (const float*)d_in[14];
    const float* w_g2    = (const float*)d_in[15];
    const float* b_g2    = (const float*)d_in[16];
    const float* w_fc    = (const float*)d_in[17];
    const float* b_fc    = (const float*)d_in[18];
    float* out = (float*)d_out;

    __half *xh, *h1, *h2, *w1f, *w1b, *w2f, *w2b;
    float *wbig, *bvec, *bc;
    cudaGetSymbolAddress((void**)&xh, g_xh);
    cudaGetSymbolAddress((void**)&h1, g_h1);
    cudaGetSymbolAddress((void**)&h2, g_h2);
    cudaGetSymbolAddress((void**)&w1f, g_w1f); cudaGetSymbolAddress((void**)&w1b, g_w1b);
    cudaGetSymbolAddress((void**)&w2f, g_w2f); cudaGetSymbolAddress((void**)&w2b, g_w2b);
    cudaGetSymbolAddress((void**)&wbig, g_wbig);
    cudaGetSymbolAddress((void**)&bvec, g_bvec);
    cudaGetSymbolAddress((void**)&bc, g_bc);

    const int GRU_SMEM = 4 * 25600 + 2 * 384 * 4;    // 105472
    cudaFuncSetAttribute(gru_fused, cudaFuncAttributeMaxDynamicSharedMemorySize, GRU_SMEM);

    dim3 blk(256);

    // prep
    cvt_h<<<((size_t)NN * 128 + 255) / 256, blk>>>(x, xh, (size_t)NN * 128);
    w_prep<<<(384 * 128 + 255) / 256, blk>>>(w_ih_f1, w1f, 128);
    w_prep<<<(384 * 128 + 255) / 256, blk>>>(w_ih_b1, w1b, 128);
    w_prep<<<(384 * 256 + 255) / 256, blk>>>(w_ih_f2, w2f, 256);
    w_prep<<<(384 * 256 + 255) / 256, blk>>>(w_ih_b2, w2b, 256);
    wbig_prep<<<1, blk>>>(w_g1, b_g1, w_g2, b_g2, w_fc, b_fc, wbig, bvec, bc);

    // GRU layer 1 (K=128): fused GEMM+gates -> h1 fp16
    gru_fused<<<dim3(NN / 128, 4), 512, GRU_SMEM>>>(
        xh, 128, w1f, w1b, b_ih_f1, b_ih_b1, b_hh_f1, b_hh_b1, h1);

    // GRU layer 2 (K=256): -> h2 fp16
    gru_fused<<<dim3(NN / 128, 4), 512, GRU_SMEM>>>(
        h1, 256, w2f, w2b, b_ih_f2, b_ih_b2, b_hh_f2, b_hh_b2, h2);

    // fused S^2 stencil + (GCN1·GCN2·fc) collapsed projection
    fc_final<<<NN / 256, blk>>>(h2, wbig, bvec, bc, out, NN);
}

// round 8
// speedup vs baseline: 4.0549x; 1.1157x over previous
#include <cuda_runtime.h>
#include <cuda_fp16.h>
#include <math.h>
#include <stdint.h>

#define NN 131072

// ---------------- static device scratch ----------------
__device__ __half g_xh [(size_t)NN * 128];
__device__ __half g_h1 [(size_t)NN * 256];
__device__ __half g_h2 [(size_t)NN * 256];
__device__ __half g_w1f[384 * 128], g_w1b[384 * 128];   // permuted layout
__device__ __half g_w2f[384 * 256], g_w2b[384 * 256];   // permuted layout
__device__ float  g_wbig[256 * 10];
__device__ float  g_bvec[10];
__device__ float  g_bc[10];

// ---------------- PTX helpers ----------------
__device__ __forceinline__ uint32_t smem_u32(const void* p) {
    uint32_t a;
    asm("{ .reg .u64 t; cvta.to.shared.u64 t, %1; cvt.u32.u64 %0, t; }" : "=r"(a) : "l"(p));
    return a;
}
__device__ __forceinline__ void cp16(uint32_t dst, const void* src) {
    asm volatile("cp.async.cg.shared.global [%0], [%1], 16;" :: "r"(dst), "l"(src));
}
__device__ __forceinline__ void cp_commit() {
    asm volatile("cp.async.commit_group;");
}
__device__ __forceinline__ void cp_wait2() {
    asm volatile("cp.async.wait_group 2;");
}
__device__ __forceinline__ void ldm_x4(uint32_t& r0, uint32_t& r1, uint32_t& r2, uint32_t& r3,
                                       uint32_t addr) {
    asm volatile("ldmatrix.sync.aligned.m8n8.x4.shared.b16 {%0,%1,%2,%3}, [%4];"
                 : "=r"(r0), "=r"(r1), "=r"(r2), "=r"(r3) : "r"(addr));
}
__device__ __forceinline__ void mma_f16(float* d, const uint32_t* a, const uint32_t* b) {
    asm volatile("mma.sync.aligned.m16n8k16.row.col.f32.f16.f16.f32 "
                 "{%0,%1,%2,%3}, {%4,%5,%6,%7}, {%8,%9}, {%0,%1,%2,%3};"
                 : "+f"(d[0]), "+f"(d[1]), "+f"(d[2]), "+f"(d[3])
                 : "r"(a[0]), "r"(a[1]), "r"(a[2]), "r"(a[3]), "r"(b[0]), "r"(b[1]));
}
__device__ __forceinline__ float sigmoidf_(float x) { return 1.f / (1.f + expf(-x)); }

// ================= fused GRU GEMM + gates (wide warp tile) =================
// A [NN,K] fp16 K-major. Wp [384,K] fp16 in PERMUTED row order:
//   orig row g*128+h  ->  new row (h>>5)*96 + g*32 + (h&31)
// CTA: 256 rows x 192 cols (2 hidden 32-blocks x {r,z,n}).
// grid.y: dir = y>>1, hb = y&1 (B row base hb*192).
// 512 threads / 16 warps: wy=wid&7 (32 rows each), wx=wid>>3 (96 cols each).
__global__ void __launch_bounds__(512, 1)
gru_fused(const __half* __restrict__ A, int K,
          const __half* __restrict__ Wp0, const __half* __restrict__ Wp1,
          const float* __restrict__ bihf, const float* __restrict__ bihb,
          const float* __restrict__ bhhf, const float* __restrict__ bhhb,
          __half* __restrict__ H)
{
    extern __shared__ char sm[];
    constexpr int AST = 80;
    constexpr int ABYTES = 256 * AST;          // 20480
    constexpr int BBYTES = 192 * AST;          // 15360
    constexpr int STAGE = ABYTES + BBYTES;     // 35840
    constexpr int BIAS_OFF = 4 * STAGE;        // 143360

    const int tid = threadIdx.x, lane = tid & 31, wid = tid >> 5;
    const int wy = wid & 7, wx = wid >> 3;
    const int mBase = blockIdx.x * 256;
    const int dir = blockIdx.y >> 1;
    const int hb = blockIdx.y & 1;
    const __half* Wp = dir ? Wp1 : Wp0;
    const float* bih = dir ? bihb : bihf;
    const float* bhh = dir ? bhhb : bhhf;
    const int rowB = hb * 192;
    const int NCH = K >> 5;

    const uint32_t sbase = smem_u32(sm);
    float* s_bih = (float*)(sm + BIAS_OFF);
    float* s_bhh = s_bih + 384;
    for (int i = tid; i < 384; i += 512) { s_bih[i] = bih[i]; s_bhh[i] = bhh[i]; }

    auto issue = [&](int c) {
        int kk = c * 32;
        uint32_t st = sbase + (c & 3) * STAGE;
        // A: 256 rows x 4 x 16B = 1024 units (2 per thread)
#pragma unroll
        for (int it = 0; it < 2; it++) {
            int u = tid + it * 512;
            cp16(st + (u >> 2) * AST + (u & 3) * 16,
                 A + (size_t)(mBase + (u >> 2)) * K + kk + (u & 3) * 8);
        }
        // B: 192 rows x 4 = 768 units
        {
            int u = tid;
            cp16(st + ABYTES + (u >> 2) * AST + (u & 3) * 16,
                 Wp + (size_t)(rowB + (u >> 2)) * K + kk + (u & 3) * 8);
        }
        if (tid < 256) {
            int u = 512 + tid;
            cp16(st + ABYTES + (u >> 2) * AST + (u & 3) * 16,
                 Wp + (size_t)(rowB + (u >> 2)) * K + kk + (u & 3) * 8);
        }
        cp_commit();
    };

    float acc[2][12][4];
#pragma unroll
    for (int i = 0; i < 2; i++)
#pragma unroll
        for (int t = 0; t < 12; t++)
#pragma unroll
            for (int q = 0; q < 4; q++) acc[i][t][q] = 0.f;

    issue(0); issue(1); issue(2);

    const uint32_t a_lrow = lane & 15, a_khalf = (lane >> 4) * 16;
    for (int c = 0; c < NCH; c++) {
        cp_wait2();
        __syncthreads();
        if (c + 3 < NCH) issue(c + 3);
        else cp_commit();            // keep group count aligned (tail-race fix)
        uint32_t st = sbase + (c & 3) * STAGE;
#pragma unroll
        for (int kh = 0; kh < 2; kh++) {
            uint32_t a[2][4];
#pragma unroll
            for (int i = 0; i < 2; i++)
                ldm_x4(a[i][0], a[i][1], a[i][2], a[i][3],
                       st + (wy * 32 + i * 16 + a_lrow) * AST + kh * 32 + a_khalf);
            uint32_t bf[12][2];
#pragma unroll
            for (int jj = 0; jj < 6; jj++) {
                uint32_t r0, r1, r2, r3;
                ldm_x4(r0, r1, r2, r3,
                       st + ABYTES + (wx * 96 + jj * 16 + a_lrow) * AST + kh * 32 + a_khalf);
                bf[2 * jj][0] = r0; bf[2 * jj][1] = r2;
                bf[2 * jj + 1][0] = r1; bf[2 * jj + 1][1] = r3;
            }
#pragma unroll
            for (int i = 0; i < 2; i++)
#pragma unroll
                for (int t = 0; t < 12; t++)
                    mma_f16(acc[i][t], a[i], bf[t]);
        }
    }

    // ---- fused gate epilogue ----
    const int s = hb * 2 + wx;                 // hidden 32-block index (0..3)
#pragma unroll
    for (int i = 0; i < 2; i++) {
#pragma unroll
        for (int t = 0; t < 4; t++) {
#pragma unroll
            for (int rp = 0; rp < 2; rp++) {
                int row = mBase + wy * 32 + i * 16 + (lane >> 2) + rp * 8;
                __half hv[2];
#pragma unroll
                for (int q = 0; q < 2; q++) {
                    int h = s * 32 + t * 8 + (lane & 3) * 2 + q;
                    float ir = acc[i][t][rp * 2 + q];
                    float iz = acc[i][t + 4][rp * 2 + q];
                    float in = acc[i][t + 8][rp * 2 + q];
                    float r  = sigmoidf_(ir + s_bih[h] + s_bhh[h]);
                    float z  = sigmoidf_(iz + s_bih[128 + h] + s_bhh[128 + h]);
                    float ng = tanhf(in + s_bih[256 + h] + r * s_bhh[256 + h]);
                    hv[q] = __float2half_rn((1.f - z) * ng);
                }
                *(__half2*)(H + (size_t)row * 256 + dir * 128 + s * 32 + t * 8 + (lane & 3) * 2) =
                    *(__half2*)hv;
            }
        }
    }
}

// ---------------- prep kernels ----------------
__global__ void cvt_h(const float* __restrict__ src, __half* __restrict__ dst, size_t n) {
    size_t i = (size_t)blockIdx.x * blockDim.x + threadIdx.x;
    if (i < n) dst[i] = __float2half_rn(src[i]);
}

// permuted GRU weight: orig row g*128+h -> new row (h>>5)*96 + g*32 + (h&31)
__global__ void w_prep(const float* __restrict__ w, __half* __restrict__ wp, int K) {
    int i = blockIdx.x * blockDim.x + threadIdx.x;
    if (i >= 384 * K) return;
    int p = i / K, k = i - p * K;
    int g = p >> 7, h = p & 127;
    int nr = (h >> 5) * 96 + g * 32 + (h & 31);
    wp[(size_t)nr * K + k] = __float2half_rn(w[i]);
}

// Wbig = Wg1 @ (Wg2 @ Wfc)  [256,10];  bvec = bg1 @ (Wg2@Wfc);  bc = bg2@Wfc + bfc
__global__ void wbig_prep(const float* __restrict__ wg1, const float* __restrict__ bg1,
                          const float* __restrict__ wg2, const float* __restrict__ bg2,
                          const float* __restrict__ wfc, const float* __restrict__ bfc,
                          float* __restrict__ Wbig, float* __restrict__ bvec,
                          float* __restrict__ bc)
{
    __shared__ float t1[1280];            // [128,10] = wg2 @ wfc
    int tid = threadIdx.x;
    for (int i = tid; i < 1280; i += 256) {
        int j = i / 10, c = i - j * 10;
        float s = 0.f;
        for (int m = 0; m < 64; m++) s += wg2[j * 64 + m] * wfc[m * 10 + c];
        t1[i] = s;
    }
    __syncthreads();
    for (int i = tid; i < 2560; i += 256) {
        int j = i / 10, c = i - j * 10;
        float s = 0.f;
        for (int k = 0; k < 128; k++) s += wg1[j * 128 + k] * t1[k * 10 + c];
        Wbig[i] = s;
    }
    if (tid < 10) {
        float s = 0.f;
        for (int k = 0; k < 128; k++) s += bg1[k] * t1[k * 10 + tid];
        bvec[tid] = s;
        float s2 = 0.f;
        for (int m = 0; m < 64; m++) s2 += bg2[m] * wfc[m * 10 + tid];
        bc[tid] = s2 + bfc[tid];
    }
}

// ================= fused S^2 stencil + final projection =================
// out[i,:] = S^2(h2)[i,:] @ Wbig + s_i*bvec + bc
__global__ void __launch_bounds__(256)
fc_final(const __half* __restrict__ h2, const float* __restrict__ Wbig,
         const float* __restrict__ bvec, const float* __restrict__ bc,
         float* __restrict__ out, int n)
{
    __shared__ float sW[2560];
    __shared__ float sbv[10], sbc[10];
    int tid = threadIdx.x;
    for (int i = tid; i < 2560; i += 256) sW[i] = Wbig[i];
    if (tid < 10) { sbv[tid] = bvec[tid]; sbc[tid] = bc[tid]; }
    __syncthreads();

    int i = blockIdx.x * 256 + tid;
    if (i >= n) return;

    auto dfun = [n](int j) -> float {
        if (j < 0 || j >= n) return 0.f;
        return rsqrtf(1.f + (float)(j > 0) + (float)(j < n - 1));
    };
    float dm2 = dfun(i - 2), dm1 = dfun(i - 1), d0 = dfun(i);
    float dp1 = dfun(i + 1), dp2 = dfun(i + 2);
    float w0 = d0 * dm2 * dm1 * dm1;
    float w1 = d0 * dm1 * (dm1 * dm1 + d0 * d0);
    float w2 = d0 * d0 * (dm1 * dm1 + d0 * d0 + dp1 * dp1);
    float w3 = d0 * dp1 * (dp1 * dp1 + d0 * d0);
    float w4 = d0 * dp2 * dp1 * dp1;
    float si = d0 * (dm1 + d0 + dp1);

    float acc[10];
#pragma unroll
    for (int c = 0; c < 10; c++) acc[c] = si * sbv[c] + sbc[c];

    int j0 = max(i - 2, 0), j1 = max(i - 1, 0);
    int j3 = min(i + 1, n - 1), j4 = min(i + 2, n - 1);
    const uint4* r0 = (const uint4*)(h2 + (size_t)j0 * 256);
    const uint4* r1 = (const uint4*)(h2 + (size_t)j1 * 256);
    const uint4* r2 = (const uint4*)(h2 + (size_t)i  * 256);
    const uint4* r3 = (const uint4*)(h2 + (size_t)j3 * 256);
    const uint4* r4 = (const uint4*)(h2 + (size_t)j4 * 256);

    for (int kb = 0; kb < 32; kb++) {
        uint4 q0 = r0[kb], q1 = r1[kb], q2 = r2[kb], q3 = r3[kb], q4 = r4[kb];
#pragma unroll
        for (int u = 0; u < 4; u++) {
            float2 f0 = __half22float2(((const __half2*)&q0)[u]);
            float2 f1 = __half22float2(((const __half2*)&q1)[u]);
            float2 f2 = __half22float2(((const __half2*)&q2)[u]);
            float2 f3 = __half22float2(((const __half2*)&q3)[u]);
            float2 f4 = __half22float2(((const __half2*)&q4)[u]);
            float zx = w0 * f0.x + w1 * f1.x + w2 * f2.x + w3 * f3.x + w4 * f4.x;
            float zy = w0 * f0.y + w1 * f1.y + w2 * f2.y + w3 * f3.y + w4 * f4.y;
            int kcol = kb * 8 + u * 2;
            const float* wA = &sW[kcol * 10];
            const float* wB = &sW[(kcol + 1) * 10];
#pragma unroll
            for (int c = 0; c < 10; c++)
                acc[c] += zx * wA[c] + zy * wB[c];
        }
    }
#pragma unroll
    for (int c = 0; c < 10; c++)
        out[(size_t)i * 10 + c] = acc[c];
}

// ---------------- launch ----------------
extern "C" void kernel_launch(void* const* d_in, const int* in_sizes, int n_in,
                              void* d_out, int out_size)
{
    const float* x       = (const float*)d_in[0];
    const float* w_ih_f1 = (const float*)d_in[1];
    const float* b_ih_f1 = (const float*)d_in[2];
    const float* b_hh_f1 = (const float*)d_in[3];
    const float* w_ih_b1 = (const float*)d_in[4];
    const float* b_ih_b1 = (const float*)d_in[5];
    const float* b_hh_b1 = (const float*)d_in[6];
    const float* w_ih_f2 = (const float*)d_in[7];
    const float* b_ih_f2 = (const float*)d_in[8];
    const float* b_hh_f2 = (const float*)d_in[9];
    const float* w_ih_b2 = (const float*)d_in[10];
    const float* b_ih_b2 = (const float*)d_in[11];
    const float* b_hh_b2 = (const float*)d_in[12];
    const float* w_g1    = (const float*)d_in[13];
    const float* b_g1    = (const float*)d_in[14];
    const float* w_g2    = (const float*)d_in[15];
    const float* b_g2    = (const float*)d_in[16];
    const float* w_fc    = (const float*)d_in[17];
    const float* b_fc    = (const float*)d_in[18];
    float* out = (float*)d_out;

    __half *xh, *h1, *h2, *w1f, *w1b, *w2f, *w2b;
    float *wbig, *bvec, *bc;
    cudaGetSymbolAddress((void**)&xh, g_xh);
    cudaGetSymbolAddress((void**)&h1, g_h1);
    cudaGetSymbolAddress((void**)&h2, g_h2);
    cudaGetSymbolAddress((void**)&w1f, g_w1f); cudaGetSymbolAddress((void**)&w1b, g_w1b);
    cudaGetSymbolAddress((void**)&w2f, g_w2f); cudaGetSymbolAddress((void**)&w2b, g_w2b);
    cudaGetSymbolAddress((void**)&wbig, g_wbig);
    cudaGetSymbolAddress((void**)&bvec, g_bvec);
    cudaGetSymbolAddress((void**)&bc, g_bc);

    const int GRU_SMEM = 4 * 35840 + 2 * 384 * 4;    // 146432
    cudaFuncSetAttribute(gru_fused, cudaFuncAttributeMaxDynamicSharedMemorySize, GRU_SMEM);

    dim3 blk(256);

    // prep
    cvt_h<<<((size_t)NN * 128 + 255) / 256, blk>>>(x, xh, (size_t)NN * 128);
    w_prep<<<(384 * 128 + 255) / 256, blk>>>(w_ih_f1, w1f, 128);
    w_prep<<<(384 * 128 + 255) / 256, blk>>>(w_ih_b1, w1b, 128);
    w_prep<<<(384 * 256 + 255) / 256, blk>>>(w_ih_f2, w2f, 256);
    w_prep<<<(384 * 256 + 255) / 256, blk>>>(w_ih_b2, w2b, 256);
    wbig_prep<<<1, blk>>>(w_g1, b_g1, w_g2, b_g2, w_fc, b_fc, wbig, bvec, bc);

    // GRU layer 1 (K=128): fused GEMM+gates -> h1 fp16
    gru_fused<<<dim3(NN / 256, 4), 512, GRU_SMEM>>>(
        xh, 128, w1f, w1b, b_ih_f1, b_ih_b1, b_hh_f1, b_hh_b1, h1);

    // GRU layer 2 (K=256): -> h2 fp16
    gru_fused<<<dim3(NN / 256, 4), 512, GRU_SMEM>>>(
        h1, 256, w2f, w2b, b_ih_f2, b_ih_b2, b_hh_f2, b_hh_b2, h2);

    // fused S^2 stencil + (GCN1·GCN2·fc) collapsed projection
    fc_final<<<NN / 256, blk>>>(h2, wbig, bvec, bc, out, NN);
}